// round 15
// baseline (speedup 1.0000x reference)
#include <cuda_runtime.h>
#include <cuda_fp16.h>
#include <math.h>
#include <stdint.h>

// Problem constants
#define B_   4
#define S_   1024
#define D_   1024
#define F_   4096
#define H_   8
#define DH_  128
#define L_   4
#define NTOK (B_ * S_)          // 4096
#define WIN_ 100
#define LFW_ 20

typedef __half  hf;
typedef __half2 hf2;

// -------------------- scratch --------------------
__device__ float g_h [NTOK * D_];
__device__ float g_q [NTOK * D_];
__device__ float g_k [NTOK * D_];
__device__ float g_v [NTOK * D_];
__device__ float g_vmean[B_ * H_ * DH_];
__device__ float g_rcos[S_ * 64];
__device__ float g_rsin[S_ * 64];

// fp16 activation buffers
__device__ hf g_xhi[NTOK * 2048];
__device__ hf g_yhi[NTOK * D_];
__device__ hf g_chi[NTOK * D_];
__device__ hf g_fhi[NTOK * F_];

// converted weights (single fp16), offsets in elements
#define WP_OFF   0u
#define QKV_OFF  2097152u
#define WO_OFF   (QKV_OFF + 4u * 3145728u)
#define W1_OFF   (WO_OFF + 4u * 1048576u)
#define W2_OFF   (W1_OFF + 4u * 4194304u)
#define WTOT     (W2_OFF + 4u * 4194304u)
__device__ hf g_w[WTOT];

// ==================== helpers ====================
__device__ __forceinline__ uint32_t smem_u32(const void* p) {
    uint32_t a;
    asm("{ .reg .u64 t; cvta.to.shared.u64 t, %1; cvt.u32.u64 %0, t; }" : "=r"(a) : "l"(p));
    return a;
}
__device__ __forceinline__ void cp16(uint32_t saddr, const void* gaddr) {
    asm volatile("cp.async.cg.shared.global [%0], [%1], 16;" :: "r"(saddr), "l"(gaddr));
}
__device__ __forceinline__ void cp_commit() {
    asm volatile("cp.async.commit_group;" ::: "memory");
}
__device__ __forceinline__ void ldsm4(uint32_t& r0, uint32_t& r1, uint32_t& r2, uint32_t& r3,
                                      uint32_t addr) {
    asm volatile("ldmatrix.sync.aligned.m8n8.x4.shared.b16 {%0,%1,%2,%3}, [%4];"
                 : "=r"(r0), "=r"(r1), "=r"(r2), "=r"(r3) : "r"(addr));
}
__device__ __forceinline__ void ldsm4t(uint32_t& r0, uint32_t& r1, uint32_t& r2, uint32_t& r3,
                                       uint32_t addr) {
    asm volatile("ldmatrix.sync.aligned.m8n8.x4.trans.shared.b16 {%0,%1,%2,%3}, [%4];"
                 : "=r"(r0), "=r"(r1), "=r"(r2), "=r"(r3) : "r"(addr));
}
__device__ __forceinline__ void mma16816(float* d, const uint32_t* a, const uint32_t* b) {
    asm volatile(
        "mma.sync.aligned.m16n8k16.row.col.f32.f16.f16.f32 "
        "{%0,%1,%2,%3}, {%4,%5,%6,%7}, {%8,%9}, {%0,%1,%2,%3};"
        : "+f"(d[0]), "+f"(d[1]), "+f"(d[2]), "+f"(d[3])
        : "r"(a[0]), "r"(a[1]), "r"(a[2]), "r"(a[3]), "r"(b[0]), "r"(b[1]));
}

// ==================== merged converter + rope table ====================
__device__ __forceinline__ void conv_plain_range(const float* in, hf* w, int blk0, int blk)
{
    float4 v[4];
    const int base = (blk - blk0) * 1024 + threadIdx.x;
#pragma unroll
    for (int r = 0; r < 4; r++) v[r] = ((const float4*)in)[base + r * 256];
#pragma unroll
    for (int r = 0; r < 4; r++) {
        int i = base + r * 256;
        ((hf2*)w)[2 * i]     = __floats2half2_rn(v[r].x, v[r].y);
        ((hf2*)w)[2 * i + 1] = __floats2half2_rn(v[r].z, v[r].w);
    }
}
// grid = 2048 (x) + 512 (Wp) + 3072 (QKV) + 9216 (Wo/W1/W2) + 256 (rope) = 15104
__global__ void __launch_bounds__(256)
conv_all(const float* __restrict__ x,   const float* __restrict__ Wp,
         const float* __restrict__ Wq,  const float* __restrict__ Wk,
         const float* __restrict__ Wv,  const float* __restrict__ Wo,
         const float* __restrict__ W1,  const float* __restrict__ W2,
         hf* __restrict__ xhi, hf* __restrict__ w,
         float* __restrict__ rc, float* __restrict__ rs)
{
    const int blk = blockIdx.x;
    if (blk < 2048) {
        conv_plain_range(x, xhi, 0, blk);
    } else if (blk < 2560) {
        conv_plain_range(Wp, w + WP_OFF, 2048, blk);
    } else if (blk < 5632) {
        const int sub = blk - 2560;
        const float* in = (sub < 1024) ? Wq : (sub < 2048) ? Wk : Wv;
        const int coff = (sub < 1024) ? 0 : (sub < 2048) ? 1024 : 2048;
        const int sub0 = (sub < 1024) ? 0 : (sub < 2048) ? 1024 : 2048;
        float4 v[4];
        const int base = (sub - sub0) * 1024 + threadIdx.x;
#pragma unroll
        for (int r = 0; r < 4; r++) v[r] = ((const float4*)in)[base + r * 256];
#pragma unroll
        for (int r = 0; r < 4; r++) {
            int i = base + r * 256;
            int row = i >> 8, c4 = i & 255;
            size_t o2 = ((size_t)row * 3072 + coff + c4 * 4) >> 1;
            ((hf2*)(w + QKV_OFF))[o2]     = __floats2half2_rn(v[r].x, v[r].y);
            ((hf2*)(w + QKV_OFF))[o2 + 1] = __floats2half2_rn(v[r].z, v[r].w);
        }
    } else if (blk < 14848) {
        const int sub = blk - 5632;
        if (sub < 1024)      conv_plain_range(Wo, w + WO_OFF, 0,    sub);
        else if (sub < 5120) conv_plain_range(W1, w + W1_OFF, 1024, sub);
        else                 conv_plain_range(W2, w + W2_OFF, 5120, sub);
    } else {
        const int idx = (blk - 14848) * 256 + threadIdx.x;   // 0..65535
        const int p = idx & 63;
        const int s = idx >> 6;
        float inv_freq = expf(-(float)p * (9.210340371976184f / 64.f));
        float ang = (float)s * inv_freq;
        float sn, cs;
        sincosf(ang, &sn, &cs);
        rc[idx] = cs;
        rs[idx] = sn;
    }
}

// ==================== pipelined fp16 GEMM (frag double-buffered) ============
#define EP_PROJ  1
#define EP_QKV   2
#define EP_RESID 3
#define EP_SILU  4

#define A_PITCH 144
#define B_PITCH 272
#define OFF_A  0
#define OFF_B  18432
#define STAGE_B 35840
#define GEMM_SMEM (2 * STAGE_B)   // 71680

__device__ __forceinline__ void stage_load(
    uint32_t stb, const hf* Ah, const hf* Bw,
    int k0, int bm, int bn, int K, int NN, int tid)
{
#pragma unroll
    for (int t = 0; t < 4; t++) {
        const int idx = t * 256 + tid;
        const int row = idx >> 3, seg = idx & 7;
        cp16(stb + OFF_A + (uint32_t)row * A_PITCH + seg * 16,
             Ah + (size_t)(bm + row) * K + k0 + seg * 8);
    }
#pragma unroll
    for (int t = 0; t < 4; t++) {
        const int idx = t * 256 + tid;
        const int row = idx >> 4, seg = idx & 15;
        cp16(stb + OFF_B + (uint32_t)row * B_PITCH + seg * 16,
             Bw + (size_t)(k0 + row) * NN + bn + seg * 8);
    }
}

__device__ __forceinline__ void load_frags(
    uint32_t stb, uint32_t aOff, uint32_t bOff, int ks,
    uint32_t aH[4][4], uint32_t bF[4][2])
{
#pragma unroll
    for (int mi = 0; mi < 4; mi++) {
        const uint32_t ad = stb + aOff + (uint32_t)mi * (16 * A_PITCH) + ks * 32;
        ldsm4(aH[mi][0], aH[mi][1], aH[mi][2], aH[mi][3], ad);
    }
#pragma unroll
    for (int bp = 0; bp < 2; bp++) {
        const uint32_t ad = stb + bOff + (uint32_t)ks * (16 * B_PITCH) + bp * 32;
        uint32_t r0, r1, r2, r3;
        ldsm4t(r0, r1, r2, r3, ad);
        bF[2 * bp][0] = r0; bF[2 * bp][1] = r1;
        bF[2 * bp + 1][0] = r2; bF[2 * bp + 1][1] = r3;
    }
}

template <int MODE>
__global__ void __launch_bounds__(256, 2)
mma_gemm(int K, int NN,
         const hf* __restrict__ Ah, const hf* __restrict__ Bw,
         const float* __restrict__ bias, const float* __restrict__ bias2,
         const float* __restrict__ bias3,
         float* __restrict__ out, hf* __restrict__ outHi, hf* __restrict__ outLo,
         const int* __restrict__ x_lengths,
         const float* __restrict__ rc, const float* __restrict__ rs)
{
    extern __shared__ char sm[];
    const uint32_t sb = smem_u32(sm);
    const int tid  = threadIdx.x;
    const int wid  = tid >> 5;
    const int lane = tid & 31;
    const int bn = blockIdx.x * 128;
    const int bm = blockIdx.y * 128;
    const int wm = wid & 1;
    const int wn = wid >> 1;

    float acc[4][4][4];
#pragma unroll
    for (int i = 0; i < 4; i++)
#pragma unroll
        for (int j = 0; j < 4; j++)
#pragma unroll
            for (int r = 0; r < 4; r++) acc[i][j][r] = 0.f;

    const int quad = lane >> 3;
    const int qr   = lane & 7;
    const uint32_t aOff = OFF_A + (uint32_t)(wm * 64 + (quad & 1) * 8 + qr) * A_PITCH + (quad >> 1) * 16;
    const uint32_t bOff = OFF_B + (uint32_t)((quad & 1) * 8 + qr) * B_PITCH
                        + (uint32_t)(wn * 32 + (quad >> 1) * 8) * 2;

    const int nch = K >> 6;

    stage_load(sb, Ah, Bw, 0, bm, bn, K, NN, tid);
    cp_commit();
    if (nch > 1) {
        stage_load(sb + STAGE_B, Ah, Bw, 64, bm, bn, K, NN, tid);
        cp_commit();
    }

    for (int c = 0; c < nch; c++) {
        if (c < nch - 1) asm volatile("cp.async.wait_group 1;" ::: "memory");
        else             asm volatile("cp.async.wait_group 0;" ::: "memory");
        __syncthreads();

        const uint32_t stb = sb + (uint32_t)(c & 1) * STAGE_B;

        uint32_t aH[2][4][4], bF[2][4][2];
        load_frags(stb, aOff, bOff, 0, aH[0], bF[0]);
        load_frags(stb, aOff, bOff, 1, aH[1], bF[1]);
#pragma unroll
        for (int ks = 0; ks < 4; ks++) {
            const int cb = ks & 1;
#pragma unroll
            for (int mi = 0; mi < 4; mi++)
#pragma unroll
                for (int ni = 0; ni < 4; ni++)
                    mma16816(acc[mi][ni], aH[cb][mi], bF[cb][ni]);
            if (ks < 2)
                load_frags(stb, aOff, bOff, ks + 2, aH[cb], bF[cb]);
        }
        __syncthreads();

        if (c + 2 < nch) {
            stage_load(stb, Ah, Bw, (c + 2) << 6, bm, bn, K, NN, tid);
            cp_commit();
        }
    }

    // ---- epilogue ----
    const int grp = lane >> 2;
    const int qc  = (lane & 3) * 2;

    if (MODE == EP_QKV) {
        float* sf = (float*)sm;   // 128 x 132 floats = 67584 B
#pragma unroll
        for (int mi = 0; mi < 4; mi++) {
#pragma unroll
            for (int ni = 0; ni < 4; ni++) {
                const int n = bn + wn * 32 + ni * 8 + qc;
                const int sel0 = n >> 10;
                const float* bp = (sel0 == 0) ? bias : (sel0 == 1) ? bias2 : bias3;
                float2 bsv = *(const float2*)(bp + (n & 1023));
                const int nl = wn * 32 + ni * 8 + qc;
#pragma unroll
                for (int half = 0; half < 2; half++) {
                    const int ml = wm * 64 + mi * 16 + grp + half * 8;
                    float2 v;
                    v.x = acc[mi][ni][2 * half + 0] + bsv.x;
                    v.y = acc[mi][ni][2 * half + 1] + bsv.y;
                    *(float2*)&sf[ml * 132 + nl] = v;
                }
            }
        }
        __syncthreads();

        const int sel = bn >> 10;
        const int hh  = (bn & 1023) >> 7;
        float* dst = (sel == 0) ? out : (sel == 1) ? (float*)outHi : (float*)outLo;
#pragma unroll
        for (int e = 0; e < 16; e++) {
            const int lin = e * 256 + tid;
            const int row = lin >> 5;
            const int dh0 = (lin & 31) * 4;
            const int sg  = bm + row;
            const int b = sg >> 10, s = sg & 1023;
            float4 xv = *(float4*)&sf[row * 132 + dh0];
            float4 o;
            if (sel == 2) {
                o = xv;
            } else {
                const int p = dh0 & 63;
                float4 pr = *(float4*)&sf[row * 132 + (dh0 ^ 64)];
                float4 cs = *(const float4*)(rc + (s << 6) + p);
                float4 sn = *(const float4*)(rs + (s << 6) + p);
                if (dh0 < 64) {
                    o.x = xv.x * cs.x - pr.x * sn.x;
                    o.y = xv.y * cs.y - pr.y * sn.y;
                    o.z = xv.z * cs.z - pr.z * sn.z;
                    o.w = xv.w * cs.w - pr.w * sn.w;
                } else {
                    o.x = pr.x * sn.x + xv.x * cs.x;
                    o.y = pr.y * sn.y + xv.y * cs.y;
                    o.z = pr.z * sn.z + xv.z * cs.z;
                    o.w = pr.w * sn.w + xv.w * cs.w;
                }
            }
            *(float4*)(dst + ((size_t)((b << 3) | hh) * 1024 + s) * 128 + dh0) = o;
        }
        return;
    }

#pragma unroll
    for (int mi = 0; mi < 4; mi++) {
        const int m0 = bm + wm * 64 + mi * 16 + grp;
#pragma unroll
        for (int ni = 0; ni < 4; ni++) {
            const int n = bn + wn * 32 + ni * 8 + qc;
            float2 bsv = *(const float2*)(bias + n);
            float2 v01, v23;
            v01.x = acc[mi][ni][0] + bsv.x;
            v01.y = acc[mi][ni][1] + bsv.y;
            v23.x = acc[mi][ni][2] + bsv.x;
            v23.y = acc[mi][ni][3] + bsv.y;
#pragma unroll
            for (int half = 0; half < 2; half++) {
                const int m = m0 + half * 8;
                float2 v = half ? v23 : v01;
                if (MODE == EP_PROJ) {
                    const int b = m >> 10, s = m & 1023;
                    const int len = x_lengths[b] >> 2;
                    if (s >= len) { v.x = 0.f; v.y = 0.f; }
                    *(float2*)(out + (size_t)m * NN + n) = v;
                } else if (MODE == EP_RESID) {
                    float2 o = *(float2*)(out + (size_t)m * NN + n);
                    o.x += v.x; o.y += v.y;
                    *(float2*)(out + (size_t)m * NN + n) = o;
                } else { // EP_SILU
                    v.x = v.x / (1.f + __expf(-v.x));
                    v.y = v.y / (1.f + __expf(-v.y));
                    const size_t o2 = ((size_t)m * NN + n) >> 1;
                    ((hf2*)outHi)[o2] = __floats2half2_rn(v.x, v.y);
                }
            }
        }
    }
}

// -------------------- LayerNorm --------------------
template <bool HFOUT>
__global__ void __launch_bounds__(256)
layernorm_kernel(const float* __restrict__ in, float* __restrict__ out,
                 hf* __restrict__ outHi,
                 const float* __restrict__ scale, const float* __restrict__ bias)
{
    __shared__ float sh1[8];
    __shared__ float sh2[8];
    const int row = blockIdx.x;
    const int t = threadIdx.x;
    const int lane = t & 31, w = t >> 5;
    const float* xr = in + (size_t)row * 1024;

    float4 vals = *(const float4*)(xr + 4 * t);
    float s = vals.x + vals.y + vals.z + vals.w;
#pragma unroll
    for (int o = 16; o; o >>= 1) s += __shfl_xor_sync(0xffffffffu, s, o);
    if (lane == 0) sh1[w] = s;
    __syncthreads();
    float tot = (t < 8) ? sh1[t] : 0.f;
    if (w == 0) {
#pragma unroll
        for (int o = 16; o; o >>= 1) tot += __shfl_xor_sync(0xffffffffu, tot, o);
        if (lane == 0) sh1[0] = tot;
    }
    __syncthreads();
    const float mean = sh1[0] * (1.f / 1024.f);

    float dx = vals.x - mean, dy = vals.y - mean, dz = vals.z - mean, dw = vals.w - mean;
    float vs = dx * dx + dy * dy + dz * dz + dw * dw;
#pragma unroll
    for (int o = 16; o; o >>= 1) vs += __shfl_xor_sync(0xffffffffu, vs, o);
    if (lane == 0) sh2[w] = vs;
    __syncthreads();
    float vtot = (t < 8) ? sh2[t] : 0.f;
    if (w == 0) {
#pragma unroll
        for (int o = 16; o; o >>= 1) vtot += __shfl_xor_sync(0xffffffffu, vtot, o);
        if (lane == 0) sh2[0] = vtot;
    }
    __syncthreads();
    const float var = sh2[0] * (1.f / 1024.f);
    const float inv = rsqrtf(var + 1e-5f);

    float4 sc = *(const float4*)(scale + 4 * t);
    float4 bi = *(const float4*)(bias + 4 * t);
    float r0 = dx * inv * sc.x + bi.x;
    float r1 = dy * inv * sc.y + bi.y;
    float r2 = dz * inv * sc.z + bi.z;
    float r3 = dw * inv * sc.w + bi.w;
    if (HFOUT) {
        hf2* dst = (hf2*)(outHi + (size_t)row * 1024 + 4 * t);
        dst[0] = __floats2half2_rn(r0, r1);
        dst[1] = __floats2half2_rn(r2, r3);
    } else {
        float4 o = {r0, r1, r2, r3};
        *(float4*)(out + (size_t)row * 1024 + 4 * t) = o;
    }
}

// -------------------- V mean --------------------
__global__ void __launch_bounds__(1024)
vmean_kernel(const float* __restrict__ v, float* __restrict__ vmean)
{
    __shared__ float partial[8][128];
    const int bh = blockIdx.x;
    const int d  = threadIdx.x & 127;
    const int sl = threadIdx.x >> 7;
    const float* base = v + (size_t)bh * S_ * DH_ + (size_t)sl * 128 * DH_ + d;
    float s = 0.f;
#pragma unroll 4
    for (int j = 0; j < 128; j++) s += base[j * DH_];
    partial[sl][d] = s;
    __syncthreads();
    if (sl == 0) {
        float t = 0.f;
#pragma unroll
        for (int r = 0; r < 8; r++) t += partial[r][d];
        vmean[bh * DH_ + d] = t * (1.f / (float)S_);
    }
}

// -------------------- windowed attention: 4 q/warp, folded, batched LDG -----
__device__ __forceinline__ float dot_fold(const float4* qv, float4 kv,
                                          int b8, int b16) {
    float s0 = qv[0].x * kv.x + qv[0].y * kv.y + qv[0].z * kv.z + qv[0].w * kv.w;
    float s1 = qv[1].x * kv.x + qv[1].y * kv.y + qv[1].z * kv.z + qv[1].w * kv.w;
    float s2 = qv[2].x * kv.x + qv[2].y * kv.y + qv[2].z * kv.z + qv[2].w * kv.w;
    float s3 = qv[3].x * kv.x + qv[3].y * kv.y + qv[3].z * kv.z + qv[3].w * kv.w;
    s0 += __shfl_xor_sync(0xffffffffu, s0, 16);
    s1 += __shfl_xor_sync(0xffffffffu, s1, 16);
    s2 += __shfl_xor_sync(0xffffffffu, s2, 16);
    s3 += __shfl_xor_sync(0xffffffffu, s3, 16);
    float cA = b16 ? s1 : s0;
    float cB = b16 ? s3 : s2;
    cA += __shfl_xor_sync(0xffffffffu, cA, 8);
    cB += __shfl_xor_sync(0xffffffffu, cB, 8);
    float d = b8 ? cB : cA;
    d += __shfl_xor_sync(0xffffffffu, d, 4);
    d += __shfl_xor_sync(0xffffffffu, d, 2);
    d += __shfl_xor_sync(0xffffffffu, d, 1);
    return d;
}

__global__ void __launch_bounds__(256)
attn_kernel(const float* __restrict__ q, const float* __restrict__ k,
            const float* __restrict__ v, const float* __restrict__ vmean,
            hf* __restrict__ ctxHi, const int* __restrict__ x_lengths)
{
    const int g    = blockIdx.x * 8 + (threadIdx.x >> 5);
    const int lane = threadIdx.x & 31;
    const int i0 = (g & 255) * 4;
    const int hh = (g >> 8) & 7;
    const int b  = g >> 11;

    const int len = x_lengths[b] >> 2;
    const size_t head = ((size_t)(b * 8 + hh)) * 1024;
    const float scale = 0.08838834764831845f;

    int jloq[4], jhq[4];
    bool msk[4];
    int lo = 0x7fffffff, hi = -1;
    bool anyLive = false, anyMasked = false;
#pragma unroll
    for (int qq = 0; qq < 4; qq++) {
        const int i = i0 + qq;
        int jl = i - (WIN_ - 1); if (jl < 0) jl = 0;
        int jh_ = i + LFW_;      if (jh_ > S_ - 1) jh_ = S_ - 1;
        if (len - 1 < jh_) jh_ = len - 1;
        jloq[qq] = jl; jhq[qq] = jh_;
        msk[qq] = (jh_ < jl);
        if (msk[qq]) anyMasked = true;
        else { anyLive = true; if (jl < lo) lo = jl; if (jh_ > hi) hi = jh_; }
    }

    float4 vmv = {0.f, 0.f, 0.f, 0.f};
    if (anyMasked)
        vmv = *(const float4*)(vmean + (b * 8 + hh) * 128 + lane * 4);

    if (!anyLive) {
#pragma unroll
        for (int qq = 0; qq < 4; qq++) {
            const size_t ob = ((size_t)(b * 1024 + i0 + qq)) * 1024 + hh * 128 + lane * 4;
            *(hf2*)(ctxHi + ob)     = __floats2half2_rn(vmv.x, vmv.y);
            *(hf2*)(ctxHi + ob + 2) = __floats2half2_rn(vmv.z, vmv.w);
        }
        return;
    }

    float4 qv[4];
#pragma unroll
    for (int qq = 0; qq < 4; qq++)
        qv[qq] = *(const float4*)(q + (head + i0 + qq) * 128 + lane * 4);

    const int pp  = lane & 7;
    const int b8  = lane & 8;
    const int b16 = lane & 16;
    const int jlo_own = b16 ? (b8 ? jloq[3] : jloq[1]) : (b8 ? jloq[2] : jloq[0]);
    const int jhi_own = b16 ? (b8 ? jhq[3] : jhq[1]) : (b8 ? jhq[2] : jhq[0]);

    float sc[4][4];
#pragma unroll
    for (int jb = 0; jb < 4; jb++)
#pragma unroll
        for (int r = 0; r < 4; r++) sc[jb][r] = -1e30f;

    // ---- phase 1: scores (batched full 8-blocks + scalar tail) ----
#pragma unroll
    for (int jb = 0; jb < 4; jb++) {
        const int jbase = lo + jb * 32;
        if (jbase > hi) break;
#pragma unroll
        for (int r = 0; r < 4; r++) {
            const int rbase = jbase + 8 * r;
            if (rbase > hi) break;
            if (rbase + 7 <= hi) {
                float4 kvb[8];
#pragma unroll
                for (int p = 0; p < 8; p++)
                    kvb[p] = *(const float4*)(k + (head + rbase + p) * 128 + lane * 4);
#pragma unroll
                for (int p = 0; p < 8; p++) {
                    float d = dot_fold(qv, kvb[p], b8, b16);
                    if (p == pp) sc[jb][r] = d * scale;
                }
            } else {
                for (int p = 0; p <= hi - rbase; p++) {
                    float4 kv = *(const float4*)(k + (head + rbase + p) * 128 + lane * 4);
                    float d = dot_fold(qv, kv, b8, b16);
                    if (p == pp) sc[jb][r] = d * scale;
                }
            }
        }
    }

    // ---- group-local softmax ----
    float m = -1e30f;
#pragma unroll
    for (int jb = 0; jb < 4; jb++)
#pragma unroll
        for (int r = 0; r < 4; r++) {
            const int j = lo + jb * 32 + 8 * r + pp;
            const bool ok = (j >= jlo_own) && (j <= jhi_own);
            const float val = ok ? sc[jb][r] : -1e30f;
            sc[jb][r] = val;
            m = fmaxf(m, val);
        }
    m = fmaxf(m, __shfl_xor_sync(0xffffffffu, m, 4));
    m = fmaxf(m, __shfl_xor_sync(0xffffffffu, m, 2));
    m = fmaxf(m, __shfl_xor_sync(0xffffffffu, m, 1));

    float l = 0.f;
#pragma unroll
    for (int jb = 0; jb < 4; jb++)
#pragma unroll
        for (int r = 0; r < 4; r++) {
            const float pe = (sc[jb][r] > -1e29f) ? __expf(sc[jb][r] - m) : 0.f;
            sc[jb][r] = pe;
            l += pe;
        }
    l += __shfl_xor_sync(0xffffffffu, l, 4);
    l += __shfl_xor_sync(0xffffffffu, l, 2);
    l += __shfl_xor_sync(0xffffffffu, l, 1);
    const float linv = 1.f / l;

    float invl[4];
    invl[0] = __shfl_sync(0xffffffffu, linv, 0);
    invl[1] = __shfl_sync(0xffffffffu, linv, 16);
    invl[2] = __shfl_sync(0xffffffffu, linv, 8);
    invl[3] = __shfl_sync(0xffffffffu, linv, 24);

    // ---- phase 2: P @ V ----
    float4 acc[4];
#pragma unroll
    for (int qq = 0; qq < 4; qq++) acc[qq] = make_float4(0.f, 0.f, 0.f, 0.f);

#pragma unroll
    for (int jb = 0; jb < 4; jb++) {
        const int jbase = lo + jb * 32;
        if (jbase > hi) break;
#pragma unroll
        for (int r = 0; r < 4; r++) {
            const int rbase = jbase + 8 * r;
            if (rbase > hi) break;
            if (rbase + 7 <= hi) {
                float4 vvb[8];
#pragma unroll
                for (int p = 0; p < 8; p++)
                    vvb[p] = *(const float4*)(v + (head + rbase + p) * 128 + lane * 4);
#pragma unroll
                for (int p = 0; p < 8; p++) {
                    const float w0 = __shfl_sync(0xffffffffu, sc[jb][r], p);
                    const float w1 = __shfl_sync(0xffffffffu, sc[jb][r], 16 + p);
                    const float w2 = __shfl_sync(0xffffffffu, sc[jb][r], 8 + p);
                    const float w3 = __shfl_sync(0xffffffffu, sc[jb][r], 24 + p);
                    acc[0].x += w0 * vvb[p].x; acc[0].y += w0 * vvb[p].y;
                    acc[0].z += w0 * vvb[p].z; acc[0].w += w0 * vvb[p].w;
                    acc[1].x += w1 * vvb[p].x; acc[1].y += w1 * vvb[p].y;
                    acc[1].z += w1 * vvb[p].z; acc[1].w += w1 * vvb[p].w;
                    acc[2].x += w2 * vvb[p].x; acc[2].y += w2 * vvb[p].y;
                    acc[2].z += w2 * vvb[p].z; acc[2].w += w2 * vvb[p].w;
                    acc[3].x += w3 * vvb[p].x; acc[3].y += w3 * vvb[p].y;
                    acc[3].z += w3 * vvb[p].z; acc[3].w += w3 * vvb[p].w;
                }
            } else {
                for (int p = 0; p <= hi - rbase; p++) {
                    float4 vv = *(const float4*)(v + (head + rbase + p) * 128 + lane * 4);
                    const float w0 = __shfl_sync(0xffffffffu, sc[jb][r], p);
                    const float w1 = __shfl_sync(0xffffffffu, sc[jb][r], 16 + p);
                    const float w2 = __shfl_sync(0xffffffffu, sc[jb][r], 8 + p);
                    const float w3 = __shfl_sync(0xffffffffu, sc[jb][r], 24 + p);
                    acc[0].x += w0 * vv.x; acc[0].y += w0 * vv.y;
                    acc[0].z += w0 * vv.z; acc[0].w += w0 * vv.w;
                    acc[1].x += w1 * vv.x; acc[1].y += w1 * vv.y;
                    acc[1].z += w1 * vv.z; acc[1].w += w1 * vv.w;
                    acc[2].x += w2 * vv.x; acc[2].y += w2 * vv.y;
                    acc[2].z += w2 * vv.z; acc[2].w += w2 * vv.w;
                    acc[3].x += w3 * vv.x; acc[3].y += w3 * vv.y;
                    acc[3].z += w3 * vv.z; acc[3].w += w3 * vv.w;
                }
            }
        }
    }

#pragma unroll
    for (int qq = 0; qq < 4; qq++) {
        const size_t ob = ((size_t)(b * 1024 + i0 + qq)) * 1024 + hh * 128 + lane * 4;
        float4 r;
        if (msk[qq]) r = vmv;
        else {
            const float il = invl[qq];
            r.x = acc[qq].x * il; r.y = acc[qq].y * il;
            r.z = acc[qq].z * il; r.w = acc[qq].w * il;
        }
        *(hf2*)(ctxHi + ob)     = __floats2half2_rn(r.x, r.y);
        *(hf2*)(ctxHi + ob + 2) = __floats2half2_rn(r.z, r.w);
    }
}

// -------------------- launch --------------------
extern "C" void kernel_launch(void* const* d_in, const int* in_sizes, int n_in,
                              void* d_out, int out_size)
{
    const float* x     = (const float*)d_in[0];
    const int*   xlen  = (const int*)  d_in[1];
    const float* Wp    = (const float*)d_in[2];
    const float* bp    = (const float*)d_in[3];
    const float* ln1_s = (const float*)d_in[4];
    const float* ln1_b = (const float*)d_in[5];
    const float* Wq    = (const float*)d_in[6];
    const float* bq    = (const float*)d_in[7];
    const float* Wk    = (const float*)d_in[8];
    const float* bk    = (const float*)d_in[9];
    const float* Wv    = (const float*)d_in[10];
    const float* bv    = (const float*)d_in[11];
    const float* Wo    = (const float*)d_in[12];
    const float* bo    = (const float*)d_in[13];
    const float* ln2_s = (const float*)d_in[14];
    const float* ln2_b = (const float*)d_in[15];
    const float* W1    = (const float*)d_in[16];
    const float* b1    = (const float*)d_in[17];
    const float* W2    = (const float*)d_in[18];
    const float* b2    = (const float*)d_in[19];
    const float* lnf_s = (const float*)d_in[20];
    const float* lnf_b = (const float*)d_in[21];
    float* out = (float*)d_out;

    float *h, *q, *k, *v, *vmean, *rc, *rs;
    hf *xhi, *yhi, *chi, *fhi, *w;
    cudaGetSymbolAddress((void**)&h,    g_h);
    cudaGetSymbolAddress((void**)&q,    g_q);
    cudaGetSymbolAddress((void**)&k,    g_k);
    cudaGetSymbolAddress((void**)&v,    g_v);
    cudaGetSymbolAddress((void**)&vmean,g_vmean);
    cudaGetSymbolAddress((void**)&rc,   g_rcos);
    cudaGetSymbolAddress((void**)&rs,   g_rsin);
    cudaGetSymbolAddress((void**)&xhi,  g_xhi);
    cudaGetSymbolAddress((void**)&yhi,  g_yhi);
    cudaGetSymbolAddress((void**)&chi,  g_chi);
    cudaGetSymbolAddress((void**)&fhi,  g_fhi);
    cudaGetSymbolAddress((void**)&w,    g_w);

    cudaFuncSetAttribute((const void*)mma_gemm<EP_PROJ>,  cudaFuncAttributeMaxDynamicSharedMemorySize, GEMM_SMEM);
    cudaFuncSetAttribute((const void*)mma_gemm<EP_QKV>,   cudaFuncAttributeMaxDynamicSharedMemorySize, GEMM_SMEM);
    cudaFuncSetAttribute((const void*)mma_gemm<EP_SILU>,  cudaFuncAttributeMaxDynamicSharedMemorySize, GEMM_SMEM);
    cudaFuncSetAttribute((const void*)mma_gemm<EP_RESID>, cudaFuncAttributeMaxDynamicSharedMemorySize, GEMM_SMEM);

    const dim3 blk(256);

    conv_all<<<15104, blk>>>(x, Wp, Wq, Wk, Wv, Wo, W1, W2, xhi, w, rc, rs);

    mma_gemm<EP_PROJ><<<dim3(8, 32), blk, GEMM_SMEM>>>(
        2048, 1024, xhi, w + WP_OFF,
        bp, nullptr, nullptr, h, nullptr, nullptr, xlen, nullptr, nullptr);

    for (int l = 0; l < L_; l++) {
        const size_t oD  = (size_t)l * D_;
        const size_t oF  = (size_t)l * F_;
        const uint32_t oQKV = QKV_OFF + (uint32_t)l * 3145728u;
        const uint32_t oWO  = WO_OFF  + (uint32_t)l * 1048576u;
        const uint32_t oW1  = W1_OFF  + (uint32_t)l * 4194304u;
        const uint32_t oW2  = W2_OFF  + (uint32_t)l * 4194304u;

        layernorm_kernel<true><<<NTOK, blk>>>(h, nullptr, yhi, ln1_s + oD, ln1_b + oD);

        mma_gemm<EP_QKV><<<dim3(24, 32), blk, GEMM_SMEM>>>(
            1024, 3072, yhi, w + oQKV,
            bq + oD, bk + oD, bv + oD, q, (hf*)k, (hf*)v, nullptr, rc, rs);

        vmean_kernel<<<B_ * H_, 1024>>>(v, vmean);
        attn_kernel<<<(B_ * H_ * S_) / 32, 256>>>(q, k, v, vmean, chi, xlen);

        mma_gemm<EP_RESID><<<dim3(8, 32), blk, GEMM_SMEM>>>(
            1024, 1024, chi, w + oWO,
            bo + oD, nullptr, nullptr, h, nullptr, nullptr, nullptr, nullptr, nullptr);

        layernorm_kernel<true><<<NTOK, blk>>>(h, nullptr, yhi, ln2_s + oD, ln2_b + oD);

        mma_gemm<EP_SILU><<<dim3(32, 32), blk, GEMM_SMEM>>>(
            1024, 4096, yhi, w + oW1,
            b1 + oF, nullptr, nullptr, nullptr, fhi, nullptr, nullptr, nullptr, nullptr);

        mma_gemm<EP_RESID><<<dim3(8, 32), blk, GEMM_SMEM>>>(
            4096, 1024, fhi, w + oW2,
            b2 + oD, nullptr, nullptr, h, nullptr, nullptr, nullptr, nullptr, nullptr);
    }

    layernorm_kernel<false><<<NTOK, blk>>>(h, out, nullptr, lnf_s, lnf_b);
}

// round 16
// speedup vs baseline: 1.0515x; 1.0515x over previous
#include <cuda_runtime.h>
#include <cuda_fp16.h>
#include <math.h>
#include <stdint.h>

// Problem constants
#define B_   4
#define S_   1024
#define D_   1024
#define F_   4096
#define H_   8
#define DH_  128
#define L_   4
#define NTOK (B_ * S_)          // 4096
#define WIN_ 100
#define LFW_ 20

typedef __half  hf;
typedef __half2 hf2;

// -------------------- scratch --------------------
__device__ float g_h [NTOK * D_];
__device__ float g_q [NTOK * D_];
__device__ float g_k [NTOK * D_];
__device__ float g_v [NTOK * D_];
__device__ float g_vmean[B_ * H_ * DH_];
__device__ float g_rcos[S_ * 64];
__device__ float g_rsin[S_ * 64];

// fp16 activation buffers
__device__ hf g_xhi[NTOK * 2048];
__device__ hf g_yhi[NTOK * D_];
__device__ hf g_chi[NTOK * D_];
__device__ hf g_fhi[NTOK * F_];

// converted weights (single fp16), offsets in elements
#define WP_OFF   0u
#define QKV_OFF  2097152u
#define WO_OFF   (QKV_OFF + 4u * 3145728u)
#define W1_OFF   (WO_OFF + 4u * 1048576u)
#define W2_OFF   (W1_OFF + 4u * 4194304u)
#define WTOT     (W2_OFF + 4u * 4194304u)
__device__ hf g_w[WTOT];

// ==================== helpers ====================
__device__ __forceinline__ uint32_t smem_u32(const void* p) {
    uint32_t a;
    asm("{ .reg .u64 t; cvta.to.shared.u64 t, %1; cvt.u32.u64 %0, t; }" : "=r"(a) : "l"(p));
    return a;
}
__device__ __forceinline__ void cp16(uint32_t saddr, const void* gaddr) {
    asm volatile("cp.async.cg.shared.global [%0], [%1], 16;" :: "r"(saddr), "l"(gaddr));
}
__device__ __forceinline__ void cp_commit() {
    asm volatile("cp.async.commit_group;" ::: "memory");
}
__device__ __forceinline__ void ldsm4(uint32_t& r0, uint32_t& r1, uint32_t& r2, uint32_t& r3,
                                      uint32_t addr) {
    asm volatile("ldmatrix.sync.aligned.m8n8.x4.shared.b16 {%0,%1,%2,%3}, [%4];"
                 : "=r"(r0), "=r"(r1), "=r"(r2), "=r"(r3) : "r"(addr));
}
__device__ __forceinline__ void ldsm4t(uint32_t& r0, uint32_t& r1, uint32_t& r2, uint32_t& r3,
                                       uint32_t addr) {
    asm volatile("ldmatrix.sync.aligned.m8n8.x4.trans.shared.b16 {%0,%1,%2,%3}, [%4];"
                 : "=r"(r0), "=r"(r1), "=r"(r2), "=r"(r3) : "r"(addr));
}
__device__ __forceinline__ void mma16816(float* d, const uint32_t* a, const uint32_t* b) {
    asm volatile(
        "mma.sync.aligned.m16n8k16.row.col.f32.f16.f16.f32 "
        "{%0,%1,%2,%3}, {%4,%5,%6,%7}, {%8,%9}, {%0,%1,%2,%3};"
        : "+f"(d[0]), "+f"(d[1]), "+f"(d[2]), "+f"(d[3])
        : "r"(a[0]), "r"(a[1]), "r"(a[2]), "r"(a[3]), "r"(b[0]), "r"(b[1]));
}

// ==================== merged converter + rope table ====================
__device__ __forceinline__ void conv_plain_range(const float* in, hf* w, int blk0, int blk)
{
    float4 v[4];
    const int base = (blk - blk0) * 1024 + threadIdx.x;
#pragma unroll
    for (int r = 0; r < 4; r++) v[r] = ((const float4*)in)[base + r * 256];
#pragma unroll
    for (int r = 0; r < 4; r++) {
        int i = base + r * 256;
        ((hf2*)w)[2 * i]     = __floats2half2_rn(v[r].x, v[r].y);
        ((hf2*)w)[2 * i + 1] = __floats2half2_rn(v[r].z, v[r].w);
    }
}
// grid = 2048 (x) + 512 (Wp) + 3072 (QKV) + 9216 (Wo/W1/W2) + 256 (rope) = 15104
__global__ void __launch_bounds__(256)
conv_all(const float* __restrict__ x,   const float* __restrict__ Wp,
         const float* __restrict__ Wq,  const float* __restrict__ Wk,
         const float* __restrict__ Wv,  const float* __restrict__ Wo,
         const float* __restrict__ W1,  const float* __restrict__ W2,
         hf* __restrict__ xhi, hf* __restrict__ w,
         float* __restrict__ rc, float* __restrict__ rs)
{
    const int blk = blockIdx.x;
    if (blk < 2048) {
        conv_plain_range(x, xhi, 0, blk);
    } else if (blk < 2560) {
        conv_plain_range(Wp, w + WP_OFF, 2048, blk);
    } else if (blk < 5632) {
        const int sub = blk - 2560;
        const float* in = (sub < 1024) ? Wq : (sub < 2048) ? Wk : Wv;
        const int coff = (sub < 1024) ? 0 : (sub < 2048) ? 1024 : 2048;
        const int sub0 = (sub < 1024) ? 0 : (sub < 2048) ? 1024 : 2048;
        float4 v[4];
        const int base = (sub - sub0) * 1024 + threadIdx.x;
#pragma unroll
        for (int r = 0; r < 4; r++) v[r] = ((const float4*)in)[base + r * 256];
#pragma unroll
        for (int r = 0; r < 4; r++) {
            int i = base + r * 256;
            int row = i >> 8, c4 = i & 255;
            size_t o2 = ((size_t)row * 3072 + coff + c4 * 4) >> 1;
            ((hf2*)(w + QKV_OFF))[o2]     = __floats2half2_rn(v[r].x, v[r].y);
            ((hf2*)(w + QKV_OFF))[o2 + 1] = __floats2half2_rn(v[r].z, v[r].w);
        }
    } else if (blk < 14848) {
        const int sub = blk - 5632;
        if (sub < 1024)      conv_plain_range(Wo, w + WO_OFF, 0,    sub);
        else if (sub < 5120) conv_plain_range(W1, w + W1_OFF, 1024, sub);
        else                 conv_plain_range(W2, w + W2_OFF, 5120, sub);
    } else {
        const int idx = (blk - 14848) * 256 + threadIdx.x;   // 0..65535
        const int p = idx & 63;
        const int s = idx >> 6;
        float inv_freq = expf(-(float)p * (9.210340371976184f / 64.f));
        float ang = (float)s * inv_freq;
        float sn, cs;
        sincosf(ang, &sn, &cs);
        rc[idx] = cs;
        rs[idx] = sn;
    }
}

// ==================== pipelined fp16 GEMM (R14 single-buffered form) ========
#define EP_PROJ  1
#define EP_QKV   2
#define EP_RESID 3
#define EP_SILU  4

#define A_PITCH 144
#define B_PITCH 272
#define OFF_AH 0
#define OFF_AL 18432
#define OFF_B  36864
#define STAGE_B 54272
#define GEMM_SMEM (2 * STAGE_B)   // 108544

template <int NT>
__device__ __forceinline__ void stage_load(
    uint32_t stb, const hf* Ah, const hf* Al, const hf* Bw,
    int k0, int bm, int bn, int K, int NN, int tid)
{
#pragma unroll
    for (int t = 0; t < 4; t++) {
        const int idx = t * 256 + tid;
        const int row = idx >> 3, seg = idx & 7;
        const size_t go = (size_t)(bm + row) * K + k0 + seg * 8;
        const uint32_t so = stb + (uint32_t)row * A_PITCH + seg * 16;
        cp16(so + OFF_AH, Ah + go);
        if (NT == 2) cp16(so + OFF_AL, Al + go);
    }
#pragma unroll
    for (int t = 0; t < 4; t++) {
        const int idx = t * 256 + tid;
        const int row = idx >> 4, seg = idx & 15;
        const size_t go = (size_t)(k0 + row) * NN + bn + seg * 8;
        const uint32_t so = stb + (uint32_t)row * B_PITCH + seg * 16;
        cp16(so + OFF_B, Bw + go);
    }
}

template <int MODE, int NT>
__global__ void __launch_bounds__(256, 2)
mma_gemm(int K, int NN,
         const hf* __restrict__ Ah, const hf* __restrict__ Al,
         const hf* __restrict__ Bw,
         const float* __restrict__ bias, const float* __restrict__ bias2,
         const float* __restrict__ bias3,
         float* __restrict__ out, hf* __restrict__ outHi, hf* __restrict__ outLo,
         const int* __restrict__ x_lengths,
         const float* __restrict__ rc, const float* __restrict__ rs)
{
    extern __shared__ char sm[];
    const uint32_t sb = smem_u32(sm);
    const int tid  = threadIdx.x;
    const int wid  = tid >> 5;
    const int lane = tid & 31;
    const int bn = blockIdx.x * 128;
    const int bm = blockIdx.y * 128;
    const int wm = wid & 1;
    const int wn = wid >> 1;

    float acc[4][4][4];
#pragma unroll
    for (int i = 0; i < 4; i++)
#pragma unroll
        for (int j = 0; j < 4; j++)
#pragma unroll
            for (int r = 0; r < 4; r++) acc[i][j][r] = 0.f;

    const int quad = lane >> 3;
    const int qr   = lane & 7;
    const uint32_t aOffH = OFF_AH + (uint32_t)(wm * 64 + (quad & 1) * 8 + qr) * A_PITCH + (quad >> 1) * 16;
    const uint32_t bOff  = OFF_B + (uint32_t)((quad & 1) * 8 + qr) * B_PITCH
                         + (uint32_t)(wn * 32 + (quad >> 1) * 8) * 2;

    const int nch = K >> 6;

    stage_load<NT>(sb, Ah, Al, Bw, 0, bm, bn, K, NN, tid);
    cp_commit();
    if (nch > 1) {
        stage_load<NT>(sb + STAGE_B, Ah, Al, Bw, 64, bm, bn, K, NN, tid);
        cp_commit();
    }

    for (int c = 0; c < nch; c++) {
        if (c < nch - 1) asm volatile("cp.async.wait_group 1;" ::: "memory");
        else             asm volatile("cp.async.wait_group 0;" ::: "memory");
        __syncthreads();

        const uint32_t stb = sb + (uint32_t)(c & 1) * STAGE_B;

#pragma unroll
        for (int ks = 0; ks < 4; ks++) {
            uint32_t aH[4][4], aL[4][4], bF[4][2];
#pragma unroll
            for (int mi = 0; mi < 4; mi++) {
                const uint32_t ad = stb + aOffH + (uint32_t)mi * (16 * A_PITCH) + ks * 32;
                ldsm4(aH[mi][0], aH[mi][1], aH[mi][2], aH[mi][3], ad);
                if (NT == 2)
                    ldsm4(aL[mi][0], aL[mi][1], aL[mi][2], aL[mi][3], ad + (OFF_AL - OFF_AH));
            }
#pragma unroll
            for (int bp = 0; bp < 2; bp++) {
                const uint32_t ad = stb + bOff + (uint32_t)ks * (16 * B_PITCH) + bp * 32;
                uint32_t r0, r1, r2, r3;
                ldsm4t(r0, r1, r2, r3, ad);
                bF[2 * bp][0] = r0; bF[2 * bp][1] = r1;
                bF[2 * bp + 1][0] = r2; bF[2 * bp + 1][1] = r3;
            }
#pragma unroll
            for (int mi = 0; mi < 4; mi++)
#pragma unroll
                for (int ni = 0; ni < 4; ni++) {
                    mma16816(acc[mi][ni], aH[mi], bF[ni]);
                    if (NT == 2) mma16816(acc[mi][ni], aL[mi], bF[ni]);
                }
        }
        __syncthreads();

        if (c + 2 < nch) {
            stage_load<NT>(stb, Ah, Al, Bw, (c + 2) << 6, bm, bn, K, NN, tid);
            cp_commit();
        }
    }

    // ---- epilogue ----
    const int grp = lane >> 2;
    const int qc  = (lane & 3) * 2;

    if (MODE == EP_QKV) {
        float* sf = (float*)sm;   // 128 x 132 floats
#pragma unroll
        for (int mi = 0; mi < 4; mi++) {
#pragma unroll
            for (int ni = 0; ni < 4; ni++) {
                const int n = bn + wn * 32 + ni * 8 + qc;
                const int sel0 = n >> 10;
                const float* bp = (sel0 == 0) ? bias : (sel0 == 1) ? bias2 : bias3;
                float2 bsv = *(const float2*)(bp + (n & 1023));
                const int nl = wn * 32 + ni * 8 + qc;
#pragma unroll
                for (int half = 0; half < 2; half++) {
                    const int ml = wm * 64 + mi * 16 + grp + half * 8;
                    float2 v;
                    v.x = acc[mi][ni][2 * half + 0] + bsv.x;
                    v.y = acc[mi][ni][2 * half + 1] + bsv.y;
                    *(float2*)&sf[ml * 132 + nl] = v;
                }
            }
        }
        __syncthreads();

        const int sel = bn >> 10;
        const int hh  = (bn & 1023) >> 7;
        float* dst = (sel == 0) ? out : (sel == 1) ? (float*)outHi : (float*)outLo;
#pragma unroll
        for (int e = 0; e < 16; e++) {
            const int lin = e * 256 + tid;
            const int row = lin >> 5;
            const int dh0 = (lin & 31) * 4;
            const int sg  = bm + row;
            const int b = sg >> 10, s = sg & 1023;
            float4 xv = *(float4*)&sf[row * 132 + dh0];
            float4 o;
            if (sel == 2) {
                o = xv;
            } else {
                const int p = dh0 & 63;
                float4 pr = *(float4*)&sf[row * 132 + (dh0 ^ 64)];
                float4 cs = *(const float4*)(rc + (s << 6) + p);
                float4 sn = *(const float4*)(rs + (s << 6) + p);
                if (dh0 < 64) {
                    o.x = xv.x * cs.x - pr.x * sn.x;
                    o.y = xv.y * cs.y - pr.y * sn.y;
                    o.z = xv.z * cs.z - pr.z * sn.z;
                    o.w = xv.w * cs.w - pr.w * sn.w;
                } else {
                    o.x = pr.x * sn.x + xv.x * cs.x;
                    o.y = pr.y * sn.y + xv.y * cs.y;
                    o.z = pr.z * sn.z + xv.z * cs.z;
                    o.w = pr.w * sn.w + xv.w * cs.w;
                }
            }
            *(float4*)(dst + ((size_t)((b << 3) | hh) * 1024 + s) * 128 + dh0) = o;
        }
        return;
    }

#pragma unroll
    for (int mi = 0; mi < 4; mi++) {
        const int m0 = bm + wm * 64 + mi * 16 + grp;
#pragma unroll
        for (int ni = 0; ni < 4; ni++) {
            const int n = bn + wn * 32 + ni * 8 + qc;
            float2 bsv = *(const float2*)(bias + n);
            float2 v01, v23;
            v01.x = acc[mi][ni][0] + bsv.x;
            v01.y = acc[mi][ni][1] + bsv.y;
            v23.x = acc[mi][ni][2] + bsv.x;
            v23.y = acc[mi][ni][3] + bsv.y;
#pragma unroll
            for (int half = 0; half < 2; half++) {
                const int m = m0 + half * 8;
                float2 v = half ? v23 : v01;
                if (MODE == EP_PROJ) {
                    const int b = m >> 10, s = m & 1023;
                    const int len = x_lengths[b] >> 2;
                    if (s >= len) { v.x = 0.f; v.y = 0.f; }
                    *(float2*)(out + (size_t)m * NN + n) = v;
                } else if (MODE == EP_RESID) {
                    float2 o = *(float2*)(out + (size_t)m * NN + n);
                    o.x += v.x; o.y += v.y;
                    *(float2*)(out + (size_t)m * NN + n) = o;
                } else { // EP_SILU
                    v.x = v.x / (1.f + __expf(-v.x));
                    v.y = v.y / (1.f + __expf(-v.y));
                    const size_t o2 = ((size_t)m * NN + n) >> 1;
                    ((hf2*)outHi)[o2] = __floats2half2_rn(v.x, v.y);
                }
            }
        }
    }
}

// -------------------- LayerNorm --------------------
template <bool HFOUT>
__global__ void __launch_bounds__(256)
layernorm_kernel(const float* __restrict__ in, float* __restrict__ out,
                 hf* __restrict__ outHi,
                 const float* __restrict__ scale, const float* __restrict__ bias)
{
    __shared__ float sh1[8];
    __shared__ float sh2[8];
    const int row = blockIdx.x;
    const int t = threadIdx.x;
    const int lane = t & 31, w = t >> 5;
    const float* xr = in + (size_t)row * 1024;

    float4 vals = *(const float4*)(xr + 4 * t);
    float s = vals.x + vals.y + vals.z + vals.w;
#pragma unroll
    for (int o = 16; o; o >>= 1) s += __shfl_xor_sync(0xffffffffu, s, o);
    if (lane == 0) sh1[w] = s;
    __syncthreads();
    float tot = (t < 8) ? sh1[t] : 0.f;
    if (w == 0) {
#pragma unroll
        for (int o = 16; o; o >>= 1) tot += __shfl_xor_sync(0xffffffffu, tot, o);
        if (lane == 0) sh1[0] = tot;
    }
    __syncthreads();
    const float mean = sh1[0] * (1.f / 1024.f);

    float dx = vals.x - mean, dy = vals.y - mean, dz = vals.z - mean, dw = vals.w - mean;
    float vs = dx * dx + dy * dy + dz * dz + dw * dw;
#pragma unroll
    for (int o = 16; o; o >>= 1) vs += __shfl_xor_sync(0xffffffffu, vs, o);
    if (lane == 0) sh2[w] = vs;
    __syncthreads();
    float vtot = (t < 8) ? sh2[t] : 0.f;
    if (w == 0) {
#pragma unroll
        for (int o = 16; o; o >>= 1) vtot += __shfl_xor_sync(0xffffffffu, vtot, o);
        if (lane == 0) sh2[0] = vtot;
    }
    __syncthreads();
    const float var = sh2[0] * (1.f / 1024.f);
    const float inv = rsqrtf(var + 1e-5f);

    float4 sc = *(const float4*)(scale + 4 * t);
    float4 bi = *(const float4*)(bias + 4 * t);
    float r0 = dx * inv * sc.x + bi.x;
    float r1 = dy * inv * sc.y + bi.y;
    float r2 = dz * inv * sc.z + bi.z;
    float r3 = dw * inv * sc.w + bi.w;
    if (HFOUT) {
        hf2* dst = (hf2*)(outHi + (size_t)row * 1024 + 4 * t);
        dst[0] = __floats2half2_rn(r0, r1);
        dst[1] = __floats2half2_rn(r2, r3);
    } else {
        float4 o = {r0, r1, r2, r3};
        *(float4*)(out + (size_t)row * 1024 + 4 * t) = o;
    }
}

// -------------------- V mean (warp-per-32-rows, float4 loads) ---------------
__global__ void __launch_bounds__(1024)
vmean_kernel(const float* __restrict__ v, float* __restrict__ vmean)
{
    __shared__ float4 partial[32][32];   // [warp][lane] = partial sum of 32 rows
    const int bh   = blockIdx.x;
    const int lane = threadIdx.x & 31;
    const int w    = threadIdx.x >> 5;   // 0..31
    const float* base = v + (size_t)bh * S_ * DH_ + (size_t)w * 32 * DH_ + lane * 4;
    float4 s = {0.f, 0.f, 0.f, 0.f};
#pragma unroll 8
    for (int j = 0; j < 32; j++) {
        float4 t = *(const float4*)(base + j * DH_);
        s.x += t.x; s.y += t.y; s.z += t.z; s.w += t.w;
    }
    partial[w][lane] = s;
    __syncthreads();
    if (w == 0) {
        float4 t = {0.f, 0.f, 0.f, 0.f};
#pragma unroll
        for (int r = 0; r < 32; r++) {
            float4 p = partial[r][lane];
            t.x += p.x; t.y += p.y; t.z += p.z; t.w += p.w;
        }
        const float inv = 1.f / (float)S_;
        t.x *= inv; t.y *= inv; t.z *= inv; t.w *= inv;
        *(float4*)(vmean + bh * DH_ + lane * 4) = t;
    }
}

// -------------------- windowed attention: 4 q/warp, folded, batched LDG -----
__device__ __forceinline__ float dot_fold(const float4* qv, float4 kv,
                                          int b8, int b16) {
    float s0 = qv[0].x * kv.x + qv[0].y * kv.y + qv[0].z * kv.z + qv[0].w * kv.w;
    float s1 = qv[1].x * kv.x + qv[1].y * kv.y + qv[1].z * kv.z + qv[1].w * kv.w;
    float s2 = qv[2].x * kv.x + qv[2].y * kv.y + qv[2].z * kv.z + qv[2].w * kv.w;
    float s3 = qv[3].x * kv.x + qv[3].y * kv.y + qv[3].z * kv.z + qv[3].w * kv.w;
    s0 += __shfl_xor_sync(0xffffffffu, s0, 16);
    s1 += __shfl_xor_sync(0xffffffffu, s1, 16);
    s2 += __shfl_xor_sync(0xffffffffu, s2, 16);
    s3 += __shfl_xor_sync(0xffffffffu, s3, 16);
    float cA = b16 ? s1 : s0;
    float cB = b16 ? s3 : s2;
    cA += __shfl_xor_sync(0xffffffffu, cA, 8);
    cB += __shfl_xor_sync(0xffffffffu, cB, 8);
    float d = b8 ? cB : cA;
    d += __shfl_xor_sync(0xffffffffu, d, 4);
    d += __shfl_xor_sync(0xffffffffu, d, 2);
    d += __shfl_xor_sync(0xffffffffu, d, 1);
    return d;
}

__global__ void __launch_bounds__(256)
attn_kernel(const float* __restrict__ q, const float* __restrict__ k,
            const float* __restrict__ v, const float* __restrict__ vmean,
            hf* __restrict__ ctxHi, const int* __restrict__ x_lengths)
{
    const int g    = blockIdx.x * 8 + (threadIdx.x >> 5);
    const int lane = threadIdx.x & 31;
    const int i0 = (g & 255) * 4;
    const int hh = (g >> 8) & 7;
    const int b  = g >> 11;

    const int len = x_lengths[b] >> 2;
    const size_t head = ((size_t)(b * 8 + hh)) * 1024;
    const float scale = 0.08838834764831845f;

    int jloq[4], jhq[4];
    bool msk[4];
    int lo = 0x7fffffff, hi = -1;
    bool anyLive = false, anyMasked = false;
#pragma unroll
    for (int qq = 0; qq < 4; qq++) {
        const int i = i0 + qq;
        int jl = i - (WIN_ - 1); if (jl < 0) jl = 0;
        int jh_ = i + LFW_;      if (jh_ > S_ - 1) jh_ = S_ - 1;
        if (len - 1 < jh_) jh_ = len - 1;
        jloq[qq] = jl; jhq[qq] = jh_;
        msk[qq] = (jh_ < jl);
        if (msk[qq]) anyMasked = true;
        else { anyLive = true; if (jl < lo) lo = jl; if (jh_ > hi) hi = jh_; }
    }

    float4 vmv = {0.f, 0.f, 0.f, 0.f};
    if (anyMasked)
        vmv = *(const float4*)(vmean + (b * 8 + hh) * 128 + lane * 4);

    if (!anyLive) {
#pragma unroll
        for (int qq = 0; qq < 4; qq++) {
            const size_t ob = ((size_t)(b * 1024 + i0 + qq)) * 1024 + hh * 128 + lane * 4;
            *(hf2*)(ctxHi + ob)     = __floats2half2_rn(vmv.x, vmv.y);
            *(hf2*)(ctxHi + ob + 2) = __floats2half2_rn(vmv.z, vmv.w);
        }
        return;
    }

    float4 qv[4];
#pragma unroll
    for (int qq = 0; qq < 4; qq++)
        qv[qq] = *(const float4*)(q + (head + i0 + qq) * 128 + lane * 4);

    const int pp  = lane & 7;
    const int b8  = lane & 8;
    const int b16 = lane & 16;
    const int jlo_own = b16 ? (b8 ? jloq[3] : jloq[1]) : (b8 ? jloq[2] : jloq[0]);
    const int jhi_own = b16 ? (b8 ? jhq[3] : jhq[1]) : (b8 ? jhq[2] : jhq[0]);

    float sc[4][4];
#pragma unroll
    for (int jb = 0; jb < 4; jb++)
#pragma unroll
        for (int r = 0; r < 4; r++) sc[jb][r] = -1e30f;

#pragma unroll
    for (int jb = 0; jb < 4; jb++) {
        const int jbase = lo + jb * 32;
        if (jbase > hi) break;
#pragma unroll
        for (int r = 0; r < 4; r++) {
            const int rbase = jbase + 8 * r;
            if (rbase > hi) break;
            if (rbase + 7 <= hi) {
                float4 kvb[8];
#pragma unroll
                for (int p = 0; p < 8; p++)
                    kvb[p] = *(const float4*)(k + (head + rbase + p) * 128 + lane * 4);
#pragma unroll
                for (int p = 0; p < 8; p++) {
                    float d = dot_fold(qv, kvb[p], b8, b16);
                    if (p == pp) sc[jb][r] = d * scale;
                }
            } else {
                for (int p = 0; p <= hi - rbase; p++) {
                    float4 kv = *(const float4*)(k + (head + rbase + p) * 128 + lane * 4);
                    float d = dot_fold(qv, kv, b8, b16);
                    if (p == pp) sc[jb][r] = d * scale;
                }
            }
        }
    }

    float m = -1e30f;
#pragma unroll
    for (int jb = 0; jb < 4; jb++)
#pragma unroll
        for (int r = 0; r < 4; r++) {
            const int j = lo + jb * 32 + 8 * r + pp;
            const bool ok = (j >= jlo_own) && (j <= jhi_own);
            const float val = ok ? sc[jb][r] : -1e30f;
            sc[jb][r] = val;
            m = fmaxf(m, val);
        }
    m = fmaxf(m, __shfl_xor_sync(0xffffffffu, m, 4));
    m = fmaxf(m, __shfl_xor_sync(0xffffffffu, m, 2));
    m = fmaxf(m, __shfl_xor_sync(0xffffffffu, m, 1));

    float l = 0.f;
#pragma unroll
    for (int jb = 0; jb < 4; jb++)
#pragma unroll
        for (int r = 0; r < 4; r++) {
            const float pe = (sc[jb][r] > -1e29f) ? __expf(sc[jb][r] - m) : 0.f;
            sc[jb][r] = pe;
            l += pe;
        }
    l += __shfl_xor_sync(0xffffffffu, l, 4);
    l += __shfl_xor_sync(0xffffffffu, l, 2);
    l += __shfl_xor_sync(0xffffffffu, l, 1);
    const float linv = 1.f / l;

    float invl[4];
    invl[0] = __shfl_sync(0xffffffffu, linv, 0);
    invl[1] = __shfl_sync(0xffffffffu, linv, 16);
    invl[2] = __shfl_sync(0xffffffffu, linv, 8);
    invl[3] = __shfl_sync(0xffffffffu, linv, 24);

    float4 acc[4];
#pragma unroll
    for (int qq = 0; qq < 4; qq++) acc[qq] = make_float4(0.f, 0.f, 0.f, 0.f);

#pragma unroll
    for (int jb = 0; jb < 4; jb++) {
        const int jbase = lo + jb * 32;
        if (jbase > hi) break;
#pragma unroll
        for (int r = 0; r < 4; r++) {
            const int rbase = jbase + 8 * r;
            if (rbase > hi) break;
            if (rbase + 7 <= hi) {
                float4 vvb[8];
#pragma unroll
                for (int p = 0; p < 8; p++)
                    vvb[p] = *(const float4*)(v + (head + rbase + p) * 128 + lane * 4);
#pragma unroll
                for (int p = 0; p < 8; p++) {
                    const float w0 = __shfl_sync(0xffffffffu, sc[jb][r], p);
                    const float w1 = __shfl_sync(0xffffffffu, sc[jb][r], 16 + p);
                    const float w2 = __shfl_sync(0xffffffffu, sc[jb][r], 8 + p);
                    const float w3 = __shfl_sync(0xffffffffu, sc[jb][r], 24 + p);
                    acc[0].x += w0 * vvb[p].x; acc[0].y += w0 * vvb[p].y;
                    acc[0].z += w0 * vvb[p].z; acc[0].w += w0 * vvb[p].w;
                    acc[1].x += w1 * vvb[p].x; acc[1].y += w1 * vvb[p].y;
                    acc[1].z += w1 * vvb[p].z; acc[1].w += w1 * vvb[p].w;
                    acc[2].x += w2 * vvb[p].x; acc[2].y += w2 * vvb[p].y;
                    acc[2].z += w2 * vvb[p].z; acc[2].w += w2 * vvb[p].w;
                    acc[3].x += w3 * vvb[p].x; acc[3].y += w3 * vvb[p].y;
                    acc[3].z += w3 * vvb[p].z; acc[3].w += w3 * vvb[p].w;
                }
            } else {
                for (int p = 0; p <= hi - rbase; p++) {
                    float4 vv = *(const float4*)(v + (head + rbase + p) * 128 + lane * 4);
                    const float w0 = __shfl_sync(0xffffffffu, sc[jb][r], p);
                    const float w1 = __shfl_sync(0xffffffffu, sc[jb][r], 16 + p);
                    const float w2 = __shfl_sync(0xffffffffu, sc[jb][r], 8 + p);
                    const float w3 = __shfl_sync(0xffffffffu, sc[jb][r], 24 + p);
                    acc[0].x += w0 * vv.x; acc[0].y += w0 * vv.y;
                    acc[0].z += w0 * vv.z; acc[0].w += w0 * vv.w;
                    acc[1].x += w1 * vv.x; acc[1].y += w1 * vv.y;
                    acc[1].z += w1 * vv.z; acc[1].w += w1 * vv.w;
                    acc[2].x += w2 * vv.x; acc[2].y += w2 * vv.y;
                    acc[2].z += w2 * vv.z; acc[2].w += w2 * vv.w;
                    acc[3].x += w3 * vv.x; acc[3].y += w3 * vv.y;
                    acc[3].z += w3 * vv.z; acc[3].w += w3 * vv.w;
                }
            }
        }
    }

#pragma unroll
    for (int qq = 0; qq < 4; qq++) {
        const size_t ob = ((size_t)(b * 1024 + i0 + qq)) * 1024 + hh * 128 + lane * 4;
        float4 r;
        if (msk[qq]) r = vmv;
        else {
            const float il = invl[qq];
            r.x = acc[qq].x * il; r.y = acc[qq].y * il;
            r.z = acc[qq].z * il; r.w = acc[qq].w * il;
        }
        *(hf2*)(ctxHi + ob)     = __floats2half2_rn(r.x, r.y);
        *(hf2*)(ctxHi + ob + 2) = __floats2half2_rn(r.z, r.w);
    }
}

// -------------------- launch --------------------
extern "C" void kernel_launch(void* const* d_in, const int* in_sizes, int n_in,
                              void* d_out, int out_size)
{
    const float* x     = (const float*)d_in[0];
    const int*   xlen  = (const int*)  d_in[1];
    const float* Wp    = (const float*)d_in[2];
    const float* bp    = (const float*)d_in[3];
    const float* ln1_s = (const float*)d_in[4];
    const float* ln1_b = (const float*)d_in[5];
    const float* Wq    = (const float*)d_in[6];
    const float* bq    = (const float*)d_in[7];
    const float* Wk    = (const float*)d_in[8];
    const float* bk    = (const float*)d_in[9];
    const float* Wv    = (const float*)d_in[10];
    const float* bv    = (const float*)d_in[11];
    const float* Wo    = (const float*)d_in[12];
    const float* bo    = (const float*)d_in[13];
    const float* ln2_s = (const float*)d_in[14];
    const float* ln2_b = (const float*)d_in[15];
    const float* W1    = (const float*)d_in[16];
    const float* b1    = (const float*)d_in[17];
    const float* W2    = (const float*)d_in[18];
    const float* b2    = (const float*)d_in[19];
    const float* lnf_s = (const float*)d_in[20];
    const float* lnf_b = (const float*)d_in[21];
    float* out = (float*)d_out;

    float *h, *q, *k, *v, *vmean, *rc, *rs;
    hf *xhi, *yhi, *chi, *fhi, *w;
    cudaGetSymbolAddress((void**)&h,    g_h);
    cudaGetSymbolAddress((void**)&q,    g_q);
    cudaGetSymbolAddress((void**)&k,    g_k);
    cudaGetSymbolAddress((void**)&v,    g_v);
    cudaGetSymbolAddress((void**)&vmean,g_vmean);
    cudaGetSymbolAddress((void**)&rc,   g_rcos);
    cudaGetSymbolAddress((void**)&rs,   g_rsin);
    cudaGetSymbolAddress((void**)&xhi,  g_xhi);
    cudaGetSymbolAddress((void**)&yhi,  g_yhi);
    cudaGetSymbolAddress((void**)&chi,  g_chi);
    cudaGetSymbolAddress((void**)&fhi,  g_fhi);
    cudaGetSymbolAddress((void**)&w,    g_w);

    cudaFuncSetAttribute((const void*)mma_gemm<EP_PROJ, 1>,  cudaFuncAttributeMaxDynamicSharedMemorySize, GEMM_SMEM);
    cudaFuncSetAttribute((const void*)mma_gemm<EP_QKV, 1>,   cudaFuncAttributeMaxDynamicSharedMemorySize, GEMM_SMEM);
    cudaFuncSetAttribute((const void*)mma_gemm<EP_SILU, 1>,  cudaFuncAttributeMaxDynamicSharedMemorySize, GEMM_SMEM);
    cudaFuncSetAttribute((const void*)mma_gemm<EP_RESID, 1>, cudaFuncAttributeMaxDynamicSharedMemorySize, GEMM_SMEM);

    const dim3 blk(256);

    conv_all<<<15104, blk>>>(x, Wp, Wq, Wk, Wv, Wo, W1, W2, xhi, w, rc, rs);

    mma_gemm<EP_PROJ, 1><<<dim3(8, 32), blk, GEMM_SMEM>>>(
        2048, 1024, xhi, nullptr, w + WP_OFF,
        bp, nullptr, nullptr, h, nullptr, nullptr, xlen, nullptr, nullptr);

    for (int l = 0; l < L_; l++) {
        const size_t oD  = (size_t)l * D_;
        const size_t oF  = (size_t)l * F_;
        const uint32_t oQKV = QKV_OFF + (uint32_t)l * 3145728u;
        const uint32_t oWO  = WO_OFF  + (uint32_t)l * 1048576u;
        const uint32_t oW1  = W1_OFF  + (uint32_t)l * 4194304u;
        const uint32_t oW2  = W2_OFF  + (uint32_t)l * 4194304u;

        layernorm_kernel<true><<<NTOK, blk>>>(h, nullptr, yhi, ln1_s + oD, ln1_b + oD);

        mma_gemm<EP_QKV, 1><<<dim3(24, 32), blk, GEMM_SMEM>>>(
            1024, 3072, yhi, nullptr, w + oQKV,
            bq + oD, bk + oD, bv + oD, q, (hf*)k, (hf*)v, nullptr, rc, rs);

        vmean_kernel<<<B_ * H_, 1024>>>(v, vmean);
        attn_kernel<<<(B_ * H_ * S_) / 32, 256>>>(q, k, v, vmean, chi, xlen);

        mma_gemm<EP_RESID, 1><<<dim3(8, 32), blk, GEMM_SMEM>>>(
            1024, 1024, chi, nullptr, w + oWO,
            bo + oD, nullptr, nullptr, h, nullptr, nullptr, nullptr, nullptr, nullptr);

        layernorm_kernel<true><<<NTOK, blk>>>(h, nullptr, yhi, ln2_s + oD, ln2_b + oD);

        mma_gemm<EP_SILU, 1><<<dim3(32, 32), blk, GEMM_SMEM>>>(
            1024, 4096, yhi, nullptr, w + oW1,
            b1 + oF, nullptr, nullptr, nullptr, fhi, nullptr, nullptr, nullptr, nullptr);

        mma_gemm<EP_RESID, 1><<<dim3(8, 32), blk, GEMM_SMEM>>>(
            4096, 1024, fhi, nullptr, w + oW2,
            b2 + oD, nullptr, nullptr, h, nullptr, nullptr, nullptr, nullptr, nullptr);
    }

    layernorm_kernel<false><<<NTOK, blk>>>(h, out, nullptr, lnf_s, lnf_b);
}

// round 17
// speedup vs baseline: 1.0539x; 1.0023x over previous
#include <cuda_runtime.h>
#include <cuda_fp16.h>
#include <math.h>
#include <stdint.h>

// Problem constants
#define B_   4
#define S_   1024
#define D_   1024
#define F_   4096
#define H_   8
#define DH_  128
#define L_   4
#define NTOK (B_ * S_)          // 4096
#define WIN_ 100
#define LFW_ 20

typedef __half  hf;
typedef __half2 hf2;

// -------------------- scratch --------------------
__device__ float g_h [NTOK * D_];
__device__ float g_q [NTOK * D_];
__device__ float g_k [NTOK * D_];
__device__ float g_v [NTOK * D_];
__device__ float g_vmean[B_ * H_ * DH_];   // accumulates SUMS; attn scales by 1/S
__device__ float g_rcos[S_ * 64];
__device__ float g_rsin[S_ * 64];

// fp16 activation buffers
__device__ hf g_xhi[NTOK * 2048];
__device__ hf g_yhi[NTOK * D_];
__device__ hf g_chi[NTOK * D_];
__device__ hf g_fhi[NTOK * F_];

// converted weights (single fp16), offsets in elements
#define WP_OFF   0u
#define QKV_OFF  2097152u
#define WO_OFF   (QKV_OFF + 4u * 3145728u)
#define W1_OFF   (WO_OFF + 4u * 1048576u)
#define W2_OFF   (W1_OFF + 4u * 4194304u)
#define WTOT     (W2_OFF + 4u * 4194304u)
__device__ hf g_w[WTOT];

// ==================== helpers ====================
__device__ __forceinline__ uint32_t smem_u32(const void* p) {
    uint32_t a;
    asm("{ .reg .u64 t; cvta.to.shared.u64 t, %1; cvt.u32.u64 %0, t; }" : "=r"(a) : "l"(p));
    return a;
}
__device__ __forceinline__ void cp16(uint32_t saddr, const void* gaddr) {
    asm volatile("cp.async.cg.shared.global [%0], [%1], 16;" :: "r"(saddr), "l"(gaddr));
}
__device__ __forceinline__ void cp_commit() {
    asm volatile("cp.async.commit_group;" ::: "memory");
}
__device__ __forceinline__ void ldsm4(uint32_t& r0, uint32_t& r1, uint32_t& r2, uint32_t& r3,
                                      uint32_t addr) {
    asm volatile("ldmatrix.sync.aligned.m8n8.x4.shared.b16 {%0,%1,%2,%3}, [%4];"
                 : "=r"(r0), "=r"(r1), "=r"(r2), "=r"(r3) : "r"(addr));
}
__device__ __forceinline__ void ldsm4t(uint32_t& r0, uint32_t& r1, uint32_t& r2, uint32_t& r3,
                                       uint32_t addr) {
    asm volatile("ldmatrix.sync.aligned.m8n8.x4.trans.shared.b16 {%0,%1,%2,%3}, [%4];"
                 : "=r"(r0), "=r"(r1), "=r"(r2), "=r"(r3) : "r"(addr));
}
__device__ __forceinline__ void mma16816(float* d, const uint32_t* a, const uint32_t* b) {
    asm volatile(
        "mma.sync.aligned.m16n8k16.row.col.f32.f16.f16.f32 "
        "{%0,%1,%2,%3}, {%4,%5,%6,%7}, {%8,%9}, {%0,%1,%2,%3};"
        : "+f"(d[0]), "+f"(d[1]), "+f"(d[2]), "+f"(d[3])
        : "r"(a[0]), "r"(a[1]), "r"(a[2]), "r"(a[3]), "r"(b[0]), "r"(b[1]));
}

// ==================== merged converter + rope table ====================
__device__ __forceinline__ void conv_plain_range(const float* in, hf* w, int blk0, int blk)
{
    float4 v[4];
    const int base = (blk - blk0) * 1024 + threadIdx.x;
#pragma unroll
    for (int r = 0; r < 4; r++) v[r] = ((const float4*)in)[base + r * 256];
#pragma unroll
    for (int r = 0; r < 4; r++) {
        int i = base + r * 256;
        ((hf2*)w)[2 * i]     = __floats2half2_rn(v[r].x, v[r].y);
        ((hf2*)w)[2 * i + 1] = __floats2half2_rn(v[r].z, v[r].w);
    }
}
// grid = 2048 (x) + 512 (Wp) + 3072 (QKV) + 9216 (Wo/W1/W2) + 256 (rope) = 15104
__global__ void __launch_bounds__(256)
conv_all(const float* __restrict__ x,   const float* __restrict__ Wp,
         const float* __restrict__ Wq,  const float* __restrict__ Wk,
         const float* __restrict__ Wv,  const float* __restrict__ Wo,
         const float* __restrict__ W1,  const float* __restrict__ W2,
         hf* __restrict__ xhi, hf* __restrict__ w,
         float* __restrict__ rc, float* __restrict__ rs)
{
    const int blk = blockIdx.x;
    if (blk < 2048) {
        conv_plain_range(x, xhi, 0, blk);
    } else if (blk < 2560) {
        conv_plain_range(Wp, w + WP_OFF, 2048, blk);
    } else if (blk < 5632) {
        const int sub = blk - 2560;
        const float* in = (sub < 1024) ? Wq : (sub < 2048) ? Wk : Wv;
        const int coff = (sub < 1024) ? 0 : (sub < 2048) ? 1024 : 2048;
        const int sub0 = (sub < 1024) ? 0 : (sub < 2048) ? 1024 : 2048;
        float4 v[4];
        const int base = (sub - sub0) * 1024 + threadIdx.x;
#pragma unroll
        for (int r = 0; r < 4; r++) v[r] = ((const float4*)in)[base + r * 256];
#pragma unroll
        for (int r = 0; r < 4; r++) {
            int i = base + r * 256;
            int row = i >> 8, c4 = i & 255;
            size_t o2 = ((size_t)row * 3072 + coff + c4 * 4) >> 1;
            ((hf2*)(w + QKV_OFF))[o2]     = __floats2half2_rn(v[r].x, v[r].y);
            ((hf2*)(w + QKV_OFF))[o2 + 1] = __floats2half2_rn(v[r].z, v[r].w);
        }
    } else if (blk < 14848) {
        const int sub = blk - 5632;
        if (sub < 1024)      conv_plain_range(Wo, w + WO_OFF, 0,    sub);
        else if (sub < 5120) conv_plain_range(W1, w + W1_OFF, 1024, sub);
        else                 conv_plain_range(W2, w + W2_OFF, 5120, sub);
    } else {
        const int idx = (blk - 14848) * 256 + threadIdx.x;   // 0..65535
        const int p = idx & 63;
        const int s = idx >> 6;
        float inv_freq = expf(-(float)p * (9.210340371976184f / 64.f));
        float ang = (float)s * inv_freq;
        float sn, cs;
        sincosf(ang, &sn, &cs);
        rc[idx] = cs;
        rs[idx] = sn;
    }
}

// ==================== pipelined fp16 GEMM ====================
#define EP_PROJ  1
#define EP_QKV   2
#define EP_RESID 3
#define EP_SILU  4

#define A_PITCH 144
#define B_PITCH 272
#define OFF_A  0
#define OFF_B  18432
#define STAGE_B 35840
#define GEMM_SMEM (2 * STAGE_B)   // 71680

__device__ __forceinline__ void stage_load(
    uint32_t stb, const hf* Ah, const hf* Bw,
    int k0, int bm, int bn, int K, int NN, int tid)
{
#pragma unroll
    for (int t = 0; t < 4; t++) {
        const int idx = t * 256 + tid;
        const int row = idx >> 3, seg = idx & 7;
        cp16(stb + OFF_A + (uint32_t)row * A_PITCH + seg * 16,
             Ah + (size_t)(bm + row) * K + k0 + seg * 8);
    }
#pragma unroll
    for (int t = 0; t < 4; t++) {
        const int idx = t * 256 + tid;
        const int row = idx >> 4, seg = idx & 15;
        cp16(stb + OFF_B + (uint32_t)row * B_PITCH + seg * 16,
             Bw + (size_t)(k0 + row) * NN + bn + seg * 8);
    }
}

template <int MODE>
__global__ void __launch_bounds__(256, 2)
mma_gemm(int K, int NN,
         const hf* __restrict__ Ah, const hf* __restrict__ Bw,
         const float* __restrict__ bias, const float* __restrict__ bias2,
         const float* __restrict__ bias3,
         float* __restrict__ out, hf* __restrict__ outHi, hf* __restrict__ outLo,
         const int* __restrict__ x_lengths,
         const float* __restrict__ rc, const float* __restrict__ rs,
         float* __restrict__ vmean)
{
    extern __shared__ char sm[];
    const uint32_t sb = smem_u32(sm);
    const int tid  = threadIdx.x;
    const int wid  = tid >> 5;
    const int lane = tid & 31;
    const int bn = blockIdx.x * 128;
    const int bm = blockIdx.y * 128;
    const int wm = wid & 1;
    const int wn = wid >> 1;

    float acc[4][4][4];
#pragma unroll
    for (int i = 0; i < 4; i++)
#pragma unroll
        for (int j = 0; j < 4; j++)
#pragma unroll
            for (int r = 0; r < 4; r++) acc[i][j][r] = 0.f;

    const int quad = lane >> 3;
    const int qr   = lane & 7;
    const uint32_t aOff = OFF_A + (uint32_t)(wm * 64 + (quad & 1) * 8 + qr) * A_PITCH + (quad >> 1) * 16;
    const uint32_t bOff = OFF_B + (uint32_t)((quad & 1) * 8 + qr) * B_PITCH
                        + (uint32_t)(wn * 32 + (quad >> 1) * 8) * 2;

    const int nch = K >> 6;

    stage_load(sb, Ah, Bw, 0, bm, bn, K, NN, tid);
    cp_commit();
    if (nch > 1) {
        stage_load(sb + STAGE_B, Ah, Bw, 64, bm, bn, K, NN, tid);
        cp_commit();
    }

    for (int c = 0; c < nch; c++) {
        if (c < nch - 1) asm volatile("cp.async.wait_group 1;" ::: "memory");
        else             asm volatile("cp.async.wait_group 0;" ::: "memory");
        __syncthreads();

        const uint32_t stb = sb + (uint32_t)(c & 1) * STAGE_B;

#pragma unroll
        for (int ks = 0; ks < 4; ks++) {
            uint32_t aH[4][4], bF[4][2];
#pragma unroll
            for (int mi = 0; mi < 4; mi++) {
                const uint32_t ad = stb + aOff + (uint32_t)mi * (16 * A_PITCH) + ks * 32;
                ldsm4(aH[mi][0], aH[mi][1], aH[mi][2], aH[mi][3], ad);
            }
#pragma unroll
            for (int bp = 0; bp < 2; bp++) {
                const uint32_t ad = stb + bOff + (uint32_t)ks * (16 * B_PITCH) + bp * 32;
                uint32_t r0, r1, r2, r3;
                ldsm4t(r0, r1, r2, r3, ad);
                bF[2 * bp][0] = r0; bF[2 * bp][1] = r1;
                bF[2 * bp + 1][0] = r2; bF[2 * bp + 1][1] = r3;
            }
#pragma unroll
            for (int mi = 0; mi < 4; mi++)
#pragma unroll
                for (int ni = 0; ni < 4; ni++)
                    mma16816(acc[mi][ni], aH[mi], bF[ni]);
        }
        __syncthreads();

        if (c + 2 < nch) {
            stage_load(stb, Ah, Bw, (c + 2) << 6, bm, bn, K, NN, tid);
            cp_commit();
        }
    }

    // ---- epilogue ----
    const int grp = lane >> 2;
    const int qc  = (lane & 3) * 2;

    if (MODE == EP_QKV) {
        float* sf = (float*)sm;   // 128 x 132 floats = 67584 B <= 71680
#pragma unroll
        for (int mi = 0; mi < 4; mi++) {
#pragma unroll
            for (int ni = 0; ni < 4; ni++) {
                const int n = bn + wn * 32 + ni * 8 + qc;
                const int sel0 = n >> 10;
                const float* bp = (sel0 == 0) ? bias : (sel0 == 1) ? bias2 : bias3;
                float2 bsv = *(const float2*)(bp + (n & 1023));
                const int nl = wn * 32 + ni * 8 + qc;
#pragma unroll
                for (int half = 0; half < 2; half++) {
                    const int ml = wm * 64 + mi * 16 + grp + half * 8;
                    float2 v;
                    v.x = acc[mi][ni][2 * half + 0] + bsv.x;
                    v.y = acc[mi][ni][2 * half + 1] + bsv.y;
                    *(float2*)&sf[ml * 132 + nl] = v;
                }
            }
        }
        __syncthreads();

        const int sel = bn >> 10;
        const int hh  = (bn & 1023) >> 7;
        float* dst = (sel == 0) ? out : (sel == 1) ? (float*)outHi : (float*)outLo;
#pragma unroll
        for (int e = 0; e < 16; e++) {
            const int lin = e * 256 + tid;
            const int row = lin >> 5;
            const int dh0 = (lin & 31) * 4;
            const int sg  = bm + row;
            const int b = sg >> 10, s = sg & 1023;
            float4 xv = *(float4*)&sf[row * 132 + dh0];
            float4 o;
            if (sel == 2) {
                o = xv;
            } else {
                const int p = dh0 & 63;
                float4 pr = *(float4*)&sf[row * 132 + (dh0 ^ 64)];
                float4 cs = *(const float4*)(rc + (s << 6) + p);
                float4 sn = *(const float4*)(rs + (s << 6) + p);
                if (dh0 < 64) {
                    o.x = xv.x * cs.x - pr.x * sn.x;
                    o.y = xv.y * cs.y - pr.y * sn.y;
                    o.z = xv.z * cs.z - pr.z * sn.z;
                    o.w = xv.w * cs.w - pr.w * sn.w;
                } else {
                    o.x = pr.x * sn.x + xv.x * cs.x;
                    o.y = pr.y * sn.y + xv.y * cs.y;
                    o.z = pr.z * sn.z + xv.z * cs.z;
                    o.w = pr.w * sn.w + xv.w * cs.w;
                }
            }
            *(float4*)(dst + ((size_t)((b << 3) | hh) * 1024 + s) * 128 + dh0) = o;
        }

        // fused vmean partial sums (V CTAs only): column sums of this 128-token tile
        if (sel == 2) {
            const int col  = tid & 127;
            const int half = tid >> 7;          // 0 or 1 -> rows [0,64) / [64,128)
            float s = 0.f;
            const int r0 = half * 64;
#pragma unroll 8
            for (int r = 0; r < 64; r++) s += sf[(r0 + r) * 132 + col];
            const int b = bm >> 10;
            atomicAdd(&vmean[((b << 3) | hh) * 128 + col], s);
        }
        return;
    }

#pragma unroll
    for (int mi = 0; mi < 4; mi++) {
        const int m0 = bm + wm * 64 + mi * 16 + grp;
#pragma unroll
        for (int ni = 0; ni < 4; ni++) {
            const int n = bn + wn * 32 + ni * 8 + qc;
            float2 bsv = *(const float2*)(bias + n);
            float2 v01, v23;
            v01.x = acc[mi][ni][0] + bsv.x;
            v01.y = acc[mi][ni][1] + bsv.y;
            v23.x = acc[mi][ni][2] + bsv.x;
            v23.y = acc[mi][ni][3] + bsv.y;
#pragma unroll
            for (int half = 0; half < 2; half++) {
                const int m = m0 + half * 8;
                float2 v = half ? v23 : v01;
                if (MODE == EP_PROJ) {
                    const int b = m >> 10, s = m & 1023;
                    const int len = x_lengths[b] >> 2;
                    if (s >= len) { v.x = 0.f; v.y = 0.f; }
                    *(float2*)(out + (size_t)m * NN + n) = v;
                } else if (MODE == EP_RESID) {
                    float2 o = *(float2*)(out + (size_t)m * NN + n);
                    o.x += v.x; o.y += v.y;
                    *(float2*)(out + (size_t)m * NN + n) = o;
                } else { // EP_SILU
                    v.x = v.x / (1.f + __expf(-v.x));
                    v.y = v.y / (1.f + __expf(-v.y));
                    const size_t o2 = ((size_t)m * NN + n) >> 1;
                    ((hf2*)outHi)[o2] = __floats2half2_rn(v.x, v.y);
                }
            }
        }
    }
}

// -------------------- LayerNorm (optionally zeroes vmean) --------------------
template <bool HFOUT>
__global__ void __launch_bounds__(256)
layernorm_kernel(const float* __restrict__ in, float* __restrict__ out,
                 hf* __restrict__ outHi,
                 const float* __restrict__ scale, const float* __restrict__ bias,
                 float* __restrict__ vzero)
{
    __shared__ float sh1[8];
    __shared__ float sh2[8];
    const int row = blockIdx.x;
    const int t = threadIdx.x;
    const int lane = t & 31, w = t >> 5;
    const float* xr = in + (size_t)row * 1024;

    // zero the vmean accumulator from the first 16 blocks (4096 floats total)
    if (HFOUT && vzero != nullptr && row < 16) {
        vzero[row * 256 + t] = 0.f;
    }

    float4 vals = *(const float4*)(xr + 4 * t);
    float s = vals.x + vals.y + vals.z + vals.w;
#pragma unroll
    for (int o = 16; o; o >>= 1) s += __shfl_xor_sync(0xffffffffu, s, o);
    if (lane == 0) sh1[w] = s;
    __syncthreads();
    float tot = (t < 8) ? sh1[t] : 0.f;
    if (w == 0) {
#pragma unroll
        for (int o = 16; o; o >>= 1) tot += __shfl_xor_sync(0xffffffffu, tot, o);
        if (lane == 0) sh1[0] = tot;
    }
    __syncthreads();
    const float mean = sh1[0] * (1.f / 1024.f);

    float dx = vals.x - mean, dy = vals.y - mean, dz = vals.z - mean, dw = vals.w - mean;
    float vs = dx * dx + dy * dy + dz * dz + dw * dw;
#pragma unroll
    for (int o = 16; o; o >>= 1) vs += __shfl_xor_sync(0xffffffffu, vs, o);
    if (lane == 0) sh2[w] = vs;
    __syncthreads();
    float vtot = (t < 8) ? sh2[t] : 0.f;
    if (w == 0) {
#pragma unroll
        for (int o = 16; o; o >>= 1) vtot += __shfl_xor_sync(0xffffffffu, vtot, o);
        if (lane == 0) sh2[0] = vtot;
    }
    __syncthreads();
    const float var = sh2[0] * (1.f / 1024.f);
    const float inv = rsqrtf(var + 1e-5f);

    float4 sc = *(const float4*)(scale + 4 * t);
    float4 bi = *(const float4*)(bias + 4 * t);
    float r0 = dx * inv * sc.x + bi.x;
    float r1 = dy * inv * sc.y + bi.y;
    float r2 = dz * inv * sc.z + bi.z;
    float r3 = dw * inv * sc.w + bi.w;
    if (HFOUT) {
        hf2* dst = (hf2*)(outHi + (size_t)row * 1024 + 4 * t);
        dst[0] = __floats2half2_rn(r0, r1);
        dst[1] = __floats2half2_rn(r2, r3);
    } else {
        float4 o = {r0, r1, r2, r3};
        *(float4*)(out + (size_t)row * 1024 + 4 * t) = o;
    }
}

// -------------------- windowed attention: 4 q/warp, folded, batched LDG -----
__device__ __forceinline__ float dot_fold(const float4* qv, float4 kv,
                                          int b8, int b16) {
    float s0 = qv[0].x * kv.x + qv[0].y * kv.y + qv[0].z * kv.z + qv[0].w * kv.w;
    float s1 = qv[1].x * kv.x + qv[1].y * kv.y + qv[1].z * kv.z + qv[1].w * kv.w;
    float s2 = qv[2].x * kv.x + qv[2].y * kv.y + qv[2].z * kv.z + qv[2].w * kv.w;
    float s3 = qv[3].x * kv.x + qv[3].y * kv.y + qv[3].z * kv.z + qv[3].w * kv.w;
    s0 += __shfl_xor_sync(0xffffffffu, s0, 16);
    s1 += __shfl_xor_sync(0xffffffffu, s1, 16);
    s2 += __shfl_xor_sync(0xffffffffu, s2, 16);
    s3 += __shfl_xor_sync(0xffffffffu, s3, 16);
    float cA = b16 ? s1 : s0;
    float cB = b16 ? s3 : s2;
    cA += __shfl_xor_sync(0xffffffffu, cA, 8);
    cB += __shfl_xor_sync(0xffffffffu, cB, 8);
    float d = b8 ? cB : cA;
    d += __shfl_xor_sync(0xffffffffu, d, 4);
    d += __shfl_xor_sync(0xffffffffu, d, 2);
    d += __shfl_xor_sync(0xffffffffu, d, 1);
    return d;
}

__global__ void __launch_bounds__(256)
attn_kernel(const float* __restrict__ q, const float* __restrict__ k,
            const float* __restrict__ v, const float* __restrict__ vmean,
            hf* __restrict__ ctxHi, const int* __restrict__ x_lengths)
{
    const int g    = blockIdx.x * 8 + (threadIdx.x >> 5);
    const int lane = threadIdx.x & 31;
    const int i0 = (g & 255) * 4;
    const int hh = (g >> 8) & 7;
    const int b  = g >> 11;

    const int len = x_lengths[b] >> 2;
    const size_t head = ((size_t)(b * 8 + hh)) * 1024;
    const float scale = 0.08838834764831845f;

    int jloq[4], jhq[4];
    bool msk[4];
    int lo = 0x7fffffff, hi = -1;
    bool anyLive = false, anyMasked = false;
#pragma unroll
    for (int qq = 0; qq < 4; qq++) {
        const int i = i0 + qq;
        int jl = i - (WIN_ - 1); if (jl < 0) jl = 0;
        int jh_ = i + LFW_;      if (jh_ > S_ - 1) jh_ = S_ - 1;
        if (len - 1 < jh_) jh_ = len - 1;
        jloq[qq] = jl; jhq[qq] = jh_;
        msk[qq] = (jh_ < jl);
        if (msk[qq]) anyMasked = true;
        else { anyLive = true; if (jl < lo) lo = jl; if (jh_ > hi) hi = jh_; }
    }

    float4 vmv = {0.f, 0.f, 0.f, 0.f};
    if (anyMasked) {
        vmv = *(const float4*)(vmean + (b * 8 + hh) * 128 + lane * 4);
        const float inv = 1.f / (float)S_;
        vmv.x *= inv; vmv.y *= inv; vmv.z *= inv; vmv.w *= inv;
    }

    if (!anyLive) {
#pragma unroll
        for (int qq = 0; qq < 4; qq++) {
            const size_t ob = ((size_t)(b * 1024 + i0 + qq)) * 1024 + hh * 128 + lane * 4;
            *(hf2*)(ctxHi + ob)     = __floats2half2_rn(vmv.x, vmv.y);
            *(hf2*)(ctxHi + ob + 2) = __floats2half2_rn(vmv.z, vmv.w);
        }
        return;
    }

    float4 qv[4];
#pragma unroll
    for (int qq = 0; qq < 4; qq++)
        qv[qq] = *(const float4*)(q + (head + i0 + qq) * 128 + lane * 4);

    const int pp  = lane & 7;
    const int b8  = lane & 8;
    const int b16 = lane & 16;
    const int jlo_own = b16 ? (b8 ? jloq[3] : jloq[1]) : (b8 ? jloq[2] : jloq[0]);
    const int jhi_own = b16 ? (b8 ? jhq[3] : jhq[1]) : (b8 ? jhq[2] : jhq[0]);

    float sc[4][4];
#pragma unroll
    for (int jb = 0; jb < 4; jb++)
#pragma unroll
        for (int r = 0; r < 4; r++) sc[jb][r] = -1e30f;

#pragma unroll
    for (int jb = 0; jb < 4; jb++) {
        const int jbase = lo + jb * 32;
        if (jbase > hi) break;
#pragma unroll
        for (int r = 0; r < 4; r++) {
            const int rbase = jbase + 8 * r;
            if (rbase > hi) break;
            if (rbase + 7 <= hi) {
                float4 kvb[8];
#pragma unroll
                for (int p = 0; p < 8; p++)
                    kvb[p] = *(const float4*)(k + (head + rbase + p) * 128 + lane * 4);
#pragma unroll
                for (int p = 0; p < 8; p++) {
                    float d = dot_fold(qv, kvb[p], b8, b16);
                    if (p == pp) sc[jb][r] = d * scale;
                }
            } else {
                for (int p = 0; p <= hi - rbase; p++) {
                    float4 kv = *(const float4*)(k + (head + rbase + p) * 128 + lane * 4);
                    float d = dot_fold(qv, kv, b8, b16);
                    if (p == pp) sc[jb][r] = d * scale;
                }
            }
        }
    }

    float m = -1e30f;
#pragma unroll
    for (int jb = 0; jb < 4; jb++)
#pragma unroll
        for (int r = 0; r < 4; r++) {
            const int j = lo + jb * 32 + 8 * r + pp;
            const bool ok = (j >= jlo_own) && (j <= jhi_own);
            const float val = ok ? sc[jb][r] : -1e30f;
            sc[jb][r] = val;
            m = fmaxf(m, val);
        }
    m = fmaxf(m, __shfl_xor_sync(0xffffffffu, m, 4));
    m = fmaxf(m, __shfl_xor_sync(0xffffffffu, m, 2));
    m = fmaxf(m, __shfl_xor_sync(0xffffffffu, m, 1));

    float l = 0.f;
#pragma unroll
    for (int jb = 0; jb < 4; jb++)
#pragma unroll
        for (int r = 0; r < 4; r++) {
            const float pe = (sc[jb][r] > -1e29f) ? __expf(sc[jb][r] - m) : 0.f;
            sc[jb][r] = pe;
            l += pe;
        }
    l += __shfl_xor_sync(0xffffffffu, l, 4);
    l += __shfl_xor_sync(0xffffffffu, l, 2);
    l += __shfl_xor_sync(0xffffffffu, l, 1);
    const float linv = 1.f / l;

    float invl[4];
    invl[0] = __shfl_sync(0xffffffffu, linv, 0);
    invl[1] = __shfl_sync(0xffffffffu, linv, 16);
    invl[2] = __shfl_sync(0xffffffffu, linv, 8);
    invl[3] = __shfl_sync(0xffffffffu, linv, 24);

    float4 acc[4];
#pragma unroll
    for (int qq = 0; qq < 4; qq++) acc[qq] = make_float4(0.f, 0.f, 0.f, 0.f);

#pragma unroll
    for (int jb = 0; jb < 4; jb++) {
        const int jbase = lo + jb * 32;
        if (jbase > hi) break;
#pragma unroll
        for (int r = 0; r < 4; r++) {
            const int rbase = jbase + 8 * r;
            if (rbase > hi) break;
            if (rbase + 7 <= hi) {
                float4 vvb[8];
#pragma unroll
                for (int p = 0; p < 8; p++)
                    vvb[p] = *(const float4*)(v + (head + rbase + p) * 128 + lane * 4);
#pragma unroll
                for (int p = 0; p < 8; p++) {
                    const float w0 = __shfl_sync(0xffffffffu, sc[jb][r], p);
                    const float w1 = __shfl_sync(0xffffffffu, sc[jb][r], 16 + p);
                    const float w2 = __shfl_sync(0xffffffffu, sc[jb][r], 8 + p);
                    const float w3 = __shfl_sync(0xffffffffu, sc[jb][r], 24 + p);
                    acc[0].x += w0 * vvb[p].x; acc[0].y += w0 * vvb[p].y;
                    acc[0].z += w0 * vvb[p].z; acc[0].w += w0 * vvb[p].w;
                    acc[1].x += w1 * vvb[p].x; acc[1].y += w1 * vvb[p].y;
                    acc[1].z += w1 * vvb[p].z; acc[1].w += w1 * vvb[p].w;
                    acc[2].x += w2 * vvb[p].x; acc[2].y += w2 * vvb[p].y;
                    acc[2].z += w2 * vvb[p].z; acc[2].w += w2 * vvb[p].w;
                    acc[3].x += w3 * vvb[p].x; acc[3].y += w3 * vvb[p].y;
                    acc[3].z += w3 * vvb[p].z; acc[3].w += w3 * vvb[p].w;
                }
            } else {
                for (int p = 0; p <= hi - rbase; p++) {
                    float4 vv = *(const float4*)(v + (head + rbase + p) * 128 + lane * 4);
                    const float w0 = __shfl_sync(0xffffffffu, sc[jb][r], p);
                    const float w1 = __shfl_sync(0xffffffffu, sc[jb][r], 16 + p);
                    const float w2 = __shfl_sync(0xffffffffu, sc[jb][r], 8 + p);
                    const float w3 = __shfl_sync(0xffffffffu, sc[jb][r], 24 + p);
                    acc[0].x += w0 * vv.x; acc[0].y += w0 * vv.y;
                    acc[0].z += w0 * vv.z; acc[0].w += w0 * vv.w;
                    acc[1].x += w1 * vv.x; acc[1].y += w1 * vv.y;
                    acc[1].z += w1 * vv.z; acc[1].w += w1 * vv.w;
                    acc[2].x += w2 * vv.x; acc[2].y += w2 * vv.y;
                    acc[2].z += w2 * vv.z; acc[2].w += w2 * vv.w;
                    acc[3].x += w3 * vv.x; acc[3].y += w3 * vv.y;
                    acc[3].z += w3 * vv.z; acc[3].w += w3 * vv.w;
                }
            }
        }
    }

#pragma unroll
    for (int qq = 0; qq < 4; qq++) {
        const size_t ob = ((size_t)(b * 1024 + i0 + qq)) * 1024 + hh * 128 + lane * 4;
        float4 r;
        if (msk[qq]) r = vmv;
        else {
            const float il = invl[qq];
            r.x = acc[qq].x * il; r.y = acc[qq].y * il;
            r.z = acc[qq].z * il; r.w = acc[qq].w * il;
        }
        *(hf2*)(ctxHi + ob)     = __floats2half2_rn(r.x, r.y);
        *(hf2*)(ctxHi + ob + 2) = __floats2half2_rn(r.z, r.w);
    }
}

// -------------------- launch --------------------
extern "C" void kernel_launch(void* const* d_in, const int* in_sizes, int n_in,
                              void* d_out, int out_size)
{
    const float* x     = (const float*)d_in[0];
    const int*   xlen  = (const int*)  d_in[1];
    const float* Wp    = (const float*)d_in[2];
    const float* bp    = (const float*)d_in[3];
    const float* ln1_s = (const float*)d_in[4];
    const float* ln1_b = (const float*)d_in[5];
    const float* Wq    = (const float*)d_in[6];
    const float* bq    = (const float*)d_in[7];
    const float* Wk    = (const float*)d_in[8];
    const float* bk    = (const float*)d_in[9];
    const float* Wv    = (const float*)d_in[10];
    const float* bv    = (const float*)d_in[11];
    const float* Wo    = (const float*)d_in[12];
    const float* bo    = (const float*)d_in[13];
    const float* ln2_s = (const float*)d_in[14];
    const float* ln2_b = (const float*)d_in[15];
    const float* W1    = (const float*)d_in[16];
    const float* b1    = (const float*)d_in[17];
    const float* W2    = (const float*)d_in[18];
    const float* b2    = (const float*)d_in[19];
    const float* lnf_s = (const float*)d_in[20];
    const float* lnf_b = (const float*)d_in[21];
    float* out = (float*)d_out;

    float *h, *q, *k, *v, *vmean, *rc, *rs;
    hf *xhi, *yhi, *chi, *fhi, *w;
    cudaGetSymbolAddress((void**)&h,    g_h);
    cudaGetSymbolAddress((void**)&q,    g_q);
    cudaGetSymbolAddress((void**)&k,    g_k);
    cudaGetSymbolAddress((void**)&v,    g_v);
    cudaGetSymbolAddress((void**)&vmean,g_vmean);
    cudaGetSymbolAddress((void**)&rc,   g_rcos);
    cudaGetSymbolAddress((void**)&rs,   g_rsin);
    cudaGetSymbolAddress((void**)&xhi,  g_xhi);
    cudaGetSymbolAddress((void**)&yhi,  g_yhi);
    cudaGetSymbolAddress((void**)&chi,  g_chi);
    cudaGetSymbolAddress((void**)&fhi,  g_fhi);
    cudaGetSymbolAddress((void**)&w,    g_w);

    cudaFuncSetAttribute((const void*)mma_gemm<EP_PROJ>,  cudaFuncAttributeMaxDynamicSharedMemorySize, GEMM_SMEM);
    cudaFuncSetAttribute((const void*)mma_gemm<EP_QKV>,   cudaFuncAttributeMaxDynamicSharedMemorySize, GEMM_SMEM);
    cudaFuncSetAttribute((const void*)mma_gemm<EP_SILU>,  cudaFuncAttributeMaxDynamicSharedMemorySize, GEMM_SMEM);
    cudaFuncSetAttribute((const void*)mma_gemm<EP_RESID>, cudaFuncAttributeMaxDynamicSharedMemorySize, GEMM_SMEM);

    const dim3 blk(256);

    conv_all<<<15104, blk>>>(x, Wp, Wq, Wk, Wv, Wo, W1, W2, xhi, w, rc, rs);

    mma_gemm<EP_PROJ><<<dim3(8, 32), blk, GEMM_SMEM>>>(
        2048, 1024, xhi, w + WP_OFF,
        bp, nullptr, nullptr, h, nullptr, nullptr, xlen, nullptr, nullptr, nullptr);

    for (int l = 0; l < L_; l++) {
        const size_t oD  = (size_t)l * D_;
        const size_t oF  = (size_t)l * F_;
        const uint32_t oQKV = QKV_OFF + (uint32_t)l * 3145728u;
        const uint32_t oWO  = WO_OFF  + (uint32_t)l * 1048576u;
        const uint32_t oW1  = W1_OFF  + (uint32_t)l * 4194304u;
        const uint32_t oW2  = W2_OFF  + (uint32_t)l * 4194304u;

        // LN1 also zeroes the vmean accumulator
        layernorm_kernel<true><<<NTOK, blk>>>(h, nullptr, yhi, ln1_s + oD, ln1_b + oD, vmean);

        // fused QKV GEMM + bias + RoPE + relayout + vmean accumulation
        mma_gemm<EP_QKV><<<dim3(24, 32), blk, GEMM_SMEM>>>(
            1024, 3072, yhi, w + oQKV,
            bq + oD, bk + oD, bv + oD, q, (hf*)k, (hf*)v, nullptr, rc, rs, vmean);

        attn_kernel<<<(B_ * H_ * S_) / 32, 256>>>(q, k, v, vmean, chi, xlen);

        mma_gemm<EP_RESID><<<dim3(8, 32), blk, GEMM_SMEM>>>(
            1024, 1024, chi, w + oWO,
            bo + oD, nullptr, nullptr, h, nullptr, nullptr, nullptr, nullptr, nullptr, nullptr);

        layernorm_kernel<true><<<NTOK, blk>>>(h, nullptr, yhi, ln2_s + oD, ln2_b + oD, nullptr);

        mma_gemm<EP_SILU><<<dim3(32, 32), blk, GEMM_SMEM>>>(
            1024, 4096, yhi, w + oW1,
            b1 + oF, nullptr, nullptr, nullptr, fhi, nullptr, nullptr, nullptr, nullptr, nullptr);

        mma_gemm<EP_RESID><<<dim3(8, 32), blk, GEMM_SMEM>>>(
            4096, 1024, fhi, w + oW2,
            b2 + oD, nullptr, nullptr, h, nullptr, nullptr, nullptr, nullptr, nullptr, nullptr);
    }

    layernorm_kernel<false><<<NTOK, blk>>>(h, out, nullptr, lnf_s, lnf_b, nullptr);
}